// round 10
// baseline (speedup 1.0000x reference)
#include <cuda_runtime.h>
#include <cstdint>
#include <cstddef>

#define BB 64
#define LL 1024
#define HH 64
#define LM1 1023
#define CH 32            // scan staging chunk (steps)
#define TPC 128          // tokens per CTA in k_tokens
#define RP 132           // padded row length (floats) for transposed smem tiles

// Scratch (device globals — the allowed scratch mechanism). Zero-initialized.
__device__ float g_k  [BB * LM1 * HH + 2 * HH];   // pre-normalized keys (row-major)
__device__ float g_v  [BB * LM1 * HH + 2 * HH];   // values (row-major)
__device__ float g_ven[BB * 1024];                // 0.16*||v||^2
__device__ float g_gam[BB * 1024];                // gamma_t = kn_t . kn_{t+1}
__device__ float g_q  [BB * HH];

// Packed f32x2 FMA
__device__ __forceinline__ float2 fma2(float2 a, float2 b, float2 c) {
    float2 d;
    asm("fma.rn.f32x2 %0, %1, %2, %3;"
        : "=l"(*reinterpret_cast<unsigned long long*>(&d))
        : "l"(*reinterpret_cast<unsigned long long*>(&a)),
          "l"(*reinterpret_cast<unsigned long long*>(&b)),
          "l"(*reinterpret_cast<unsigned long long*>(&c)));
    return d;
}

__device__ __forceinline__ void cp16(uint32_t dst, const void* src) {
    asm volatile("cp.async.cg.shared.global [%0], [%1], 16;" :: "r"(dst), "l"(src));
}

// Shared-memory float offsets for k_tokens (total 50496 floats = 197.25 KB)
#define OFF_WA   0        /* 8192: W1 [64][128], later KV-combined [64][128] */
#define OFF_WB   8192     /* 8192: W2 [128][64] */
#define OFF_HT   16384    /* 8448: h^T / hn^T  [64][RP] */
#define OFF_ST   24832    /* 16896: s^T / kv^T [128][RP] */
#define OFF_FFT  41728    /* 8448: ff^T [64][RP] */
#define OFF_B1   50176    /* 128 */
#define OFF_B2   50304    /* 64 */
#define OFF_G    50368    /* 64 */
#define OFF_BT   50432    /* 64 */
#define SMEM_TOK_FLOATS 50496

// ---------------------------------------------------------------------------
// Kernel 1: cooperative register-tiled GEMM pipeline (unchanged from R8).
// ---------------------------------------------------------------------------
__global__ __launch_bounds__(256, 1)
void k_tokens(const int*   __restrict__ seq,
              const float* __restrict__ embedW,
              const float* __restrict__ W1,   // [64][128]
              const float* __restrict__ b1,   // [128]
              const float* __restrict__ W2,   // [128][64]
              const float* __restrict__ b2,   // [64]
              const float* __restrict__ lng,
              const float* __restrict__ lnb,
              const float* __restrict__ kpW,  // [64][64]
              const float* __restrict__ vpW,  // [64][64]
              const float* __restrict__ qpW)  // [64][64]
{
    extern __shared__ float sm[];
    const int tid = threadIdx.x;
    const int cta = blockIdx.x;
    const int b = cta >> 3;
    const int tbase = (cta & 7) * TPC;

    const uint32_t smA = (uint32_t)__cvta_generic_to_shared(sm + OFF_WA);
    const uint32_t smB = (uint32_t)__cvta_generic_to_shared(sm + OFF_WB);

    #pragma unroll
    for (int r = 0; r < 8; r++) {
        cp16(smA + (tid + 256 * r) * 16, (const char*)W1 + (tid + 256 * r) * 16);
        cp16(smB + (tid + 256 * r) * 16, (const char*)W2 + (tid + 256 * r) * 16);
    }
    asm volatile("cp.async.commit_group;" ::: "memory");

    if (tid < 128) sm[OFF_B1 + tid] = b1[tid];
    if (tid < 64) {
        sm[OFF_B2 + tid] = b2[tid];
        sm[OFF_G  + tid] = lng[tid];
        sm[OFF_BT + tid] = lnb[tid];
    }

    const int tok  = tid >> 1;
    const int half = tid & 1;
    {
        const int sidx = seq[(b << 10) + tbase + tok];
        const float4* e4 = reinterpret_cast<const float4*>(embedW + (sidx << 6) + half * 32);
        float* ht = sm + OFF_HT;
        #pragma unroll
        for (int r = 0; r < 8; r++) {
            float4 w = e4[r];
            int k = half * 32 + r * 4;
            ht[(k + 0) * RP + tok] = w.x;
            ht[(k + 1) * RP + tok] = w.y;
            ht[(k + 2) * RP + tok] = w.z;
            ht[(k + 3) * RP + tok] = w.w;
        }
    }
    asm volatile("cp.async.wait_group 0;" ::: "memory");
    __syncthreads();

    // ---- GEMM1 -----------------------------------------------------------
    {
        const int m0 = (tid & 15) * 8;
        const int n0 = (tid >> 4) * 8;
        float2 c1[8][4];
        #pragma unroll
        for (int ni = 0; ni < 8; ni++)
            #pragma unroll
            for (int mj = 0; mj < 4; mj++) c1[ni][mj] = make_float2(0.f, 0.f);

        const float4* ht4 = reinterpret_cast<const float4*>(sm + OFF_HT);
        const float4* w14 = reinterpret_cast<const float4*>(sm + OFF_WA);
        #pragma unroll 4
        for (int k = 0; k < 64; k++) {
            const float4 a0 = ht4[k * (RP / 4) + m0 / 4];
            const float4 a1 = ht4[k * (RP / 4) + m0 / 4 + 1];
            const float2 am[4] = { {a0.x, a0.y}, {a0.z, a0.w}, {a1.x, a1.y}, {a1.z, a1.w} };
            const float4 b0 = w14[k * 32 + n0 / 4];
            const float4 bq = w14[k * 32 + n0 / 4 + 1];
            const float bn[8] = { b0.x, b0.y, b0.z, b0.w, bq.x, bq.y, bq.z, bq.w };
            #pragma unroll
            for (int ni = 0; ni < 8; ni++) {
                const float2 bb = make_float2(bn[ni], bn[ni]);
                #pragma unroll
                for (int mj = 0; mj < 4; mj++)
                    c1[ni][mj] = fma2(bb, am[mj], c1[ni][mj]);
            }
        }
        float4* st4 = reinterpret_cast<float4*>(sm + OFF_ST);
        #pragma unroll
        for (int ni = 0; ni < 8; ni++) {
            const float bb = sm[OFF_B1 + n0 + ni];
            float2 r0 = c1[ni][0], r1 = c1[ni][1], r2 = c1[ni][2], r3 = c1[ni][3];
            r0.x = fmaxf(r0.x + bb, 0.f); r0.y = fmaxf(r0.y + bb, 0.f);
            r1.x = fmaxf(r1.x + bb, 0.f); r1.y = fmaxf(r1.y + bb, 0.f);
            r2.x = fmaxf(r2.x + bb, 0.f); r2.y = fmaxf(r2.y + bb, 0.f);
            r3.x = fmaxf(r3.x + bb, 0.f); r3.y = fmaxf(r3.y + bb, 0.f);
            st4[(n0 + ni) * (RP / 4) + m0 / 4]     = make_float4(r0.x, r0.y, r1.x, r1.y);
            st4[(n0 + ni) * (RP / 4) + m0 / 4 + 1] = make_float4(r2.x, r2.y, r3.x, r3.y);
        }
    }
    __syncthreads();

    // ---- prefetch KV-combined weights [64][128] (2048 float4s) -----------
    {
        #pragma unroll
        for (int r = 0; r < 8; r++) {
            const int f = tid + 256 * r;        // 0..2047
            const int k = f >> 5;               // 0..63
            const int c4 = f & 31;
            const char* src = (c4 < 16)
                ? (const char*)kpW + (k * 16 + c4) * 16
                : (const char*)vpW + (k * 16 + (c4 - 16)) * 16;
            cp16(smA + f * 16, src);
        }
        asm volatile("cp.async.commit_group;" ::: "memory");
    }

    // ---- GEMM2 -----------------------------------------------------------
    {
        const int m0 = (tid >> 4) * 8;
        const int n0 = (tid & 15) * 4;
        float2 c2[4][4];
        #pragma unroll
        for (int ni = 0; ni < 4; ni++)
            #pragma unroll
            for (int mj = 0; mj < 4; mj++) c2[ni][mj] = make_float2(0.f, 0.f);

        const float4* st4 = reinterpret_cast<const float4*>(sm + OFF_ST);
        const float4* w24 = reinterpret_cast<const float4*>(sm + OFF_WB);
        #pragma unroll 4
        for (int k = 0; k < 128; k++) {
            const float4 a0 = st4[k * (RP / 4) + m0 / 4];
            const float4 a1 = st4[k * (RP / 4) + m0 / 4 + 1];
            const float2 am[4] = { {a0.x, a0.y}, {a0.z, a0.w}, {a1.x, a1.y}, {a1.z, a1.w} };
            const float4 b0 = w24[k * 16 + n0 / 4];
            const float bn[4] = { b0.x, b0.y, b0.z, b0.w };
            #pragma unroll
            for (int ni = 0; ni < 4; ni++) {
                const float2 bb = make_float2(bn[ni], bn[ni]);
                #pragma unroll
                for (int mj = 0; mj < 4; mj++)
                    c2[ni][mj] = fma2(bb, am[mj], c2[ni][mj]);
            }
        }
        float4* ff4 = reinterpret_cast<float4*>(sm + OFF_FFT);
        #pragma unroll
        for (int ni = 0; ni < 4; ni++) {
            const float bb = sm[OFF_B2 + n0 + ni];
            float2 r0 = c2[ni][0], r1 = c2[ni][1], r2 = c2[ni][2], r3 = c2[ni][3];
            r0.x += bb; r0.y += bb; r1.x += bb; r1.y += bb;
            r2.x += bb; r2.y += bb; r3.x += bb; r3.y += bb;
            ff4[(n0 + ni) * (RP / 4) + m0 / 4]     = make_float4(r0.x, r0.y, r1.x, r1.y);
            ff4[(n0 + ni) * (RP / 4) + m0 / 4 + 1] = make_float4(r2.x, r2.y, r3.x, r3.y);
        }
    }
    __syncthreads();

    // ---- LayerNorm per token ---------------------------------------------
    {
        float x[32];
        const float* ht = sm + OFF_HT;
        const float* ff = sm + OFF_FFT;
        #pragma unroll
        for (int j = 0; j < 32; j++) {
            const int k = half * 32 + j;
            x[j] = ht[k * RP + tok] + ff[k * RP + tok];
        }
        float s1 = 0.f;
        #pragma unroll
        for (int j = 0; j < 32; j++) s1 += x[j];
        s1 += __shfl_xor_sync(0xffffffffu, s1, 1);
        const float mu = s1 * (1.0f / 64.0f);
        float s2 = 0.f;
        #pragma unroll
        for (int j = 0; j < 32; j++) { const float dx = x[j] - mu; s2 += dx * dx; }
        s2 += __shfl_xor_sync(0xffffffffu, s2, 1);
        const float inv = 1.0f / sqrtf(s2 * (1.0f / 64.0f) + 1e-5f);
        float* hw = sm + OFF_HT;
        #pragma unroll
        for (int j = 0; j < 32; j++) {
            const int k = half * 32 + j;
            hw[k * RP + tok] = (x[j] - mu) * inv * sm[OFF_G + k] + sm[OFF_BT + k];
        }
    }
    asm volatile("cp.async.wait_group 0;" ::: "memory");
    __syncthreads();

    // ---- GEMM3: K|V ------------------------------------------------------
    {
        const int m0 = (tid & 15) * 8;
        const int n0 = (tid >> 4) * 8;
        float2 c3[8][4];
        #pragma unroll
        for (int ni = 0; ni < 8; ni++)
            #pragma unroll
            for (int mj = 0; mj < 4; mj++) c3[ni][mj] = make_float2(0.f, 0.f);

        const float4* ht4 = reinterpret_cast<const float4*>(sm + OFF_HT);
        const float4* wk4 = reinterpret_cast<const float4*>(sm + OFF_WA);
        #pragma unroll 4
        for (int k = 0; k < 64; k++) {
            const float4 a0 = ht4[k * (RP / 4) + m0 / 4];
            const float4 a1 = ht4[k * (RP / 4) + m0 / 4 + 1];
            const float2 am[4] = { {a0.x, a0.y}, {a0.z, a0.w}, {a1.x, a1.y}, {a1.z, a1.w} };
            const float4 b0 = wk4[k * 32 + n0 / 4];
            const float4 bq = wk4[k * 32 + n0 / 4 + 1];
            const float bn[8] = { b0.x, b0.y, b0.z, b0.w, bq.x, bq.y, bq.z, bq.w };
            #pragma unroll
            for (int ni = 0; ni < 8; ni++) {
                const float2 bb = make_float2(bn[ni], bn[ni]);
                #pragma unroll
                for (int mj = 0; mj < 4; mj++)
                    c3[ni][mj] = fma2(bb, am[mj], c3[ni][mj]);
            }
        }
        float4* kv4 = reinterpret_cast<float4*>(sm + OFF_ST);
        #pragma unroll
        for (int ni = 0; ni < 8; ni++) {
            const float2 r0 = c3[ni][0], r1 = c3[ni][1], r2 = c3[ni][2], r3 = c3[ni][3];
            kv4[(n0 + ni) * (RP / 4) + m0 / 4]     = make_float4(r0.x, r0.y, r1.x, r1.y);
            kv4[(n0 + ni) * (RP / 4) + m0 / 4 + 1] = make_float4(r2.x, r2.y, r3.x, r3.y);
        }
    }
    __syncthreads();

    // ---- k-normalize, ven, stores ----------------------------------------
    {
        const int t = tbase + tok;
        const float* kv = sm + OFF_ST;
        float kvv[32];
        float nk = 0.f;
        #pragma unroll
        for (int j = 0; j < 32; j++) {
            kvv[j] = kv[(half * 32 + j) * RP + tok];
            nk = fmaf(kvv[j], kvv[j], nk);
        }
        nk += __shfl_xor_sync(0xffffffffu, nk, 1);
        const float kinv = 1.0f / fmaxf(sqrtf(nk), 1e-12f);
        if (t < LM1) {
            const size_t base = ((size_t)(b * LM1 + t)) << 6;
            float4* gk4 = reinterpret_cast<float4*>(g_k + base + half * 32);
            #pragma unroll
            for (int j4 = 0; j4 < 8; j4++) {
                gk4[j4] = make_float4(kvv[4 * j4] * kinv, kvv[4 * j4 + 1] * kinv,
                                      kvv[4 * j4 + 2] * kinv, kvv[4 * j4 + 3] * kinv);
            }
        }
        float nv = 0.f;
        #pragma unroll
        for (int j = 0; j < 32; j++) {
            kvv[j] = kv[(64 + half * 32 + j) * RP + tok];
            nv = fmaf(kvv[j], kvv[j], nv);
        }
        const float nvt = nv + __shfl_xor_sync(0xffffffffu, nv, 1);
        if (t < LM1) {
            const size_t base = ((size_t)(b * LM1 + t)) << 6;
            float4* gv4 = reinterpret_cast<float4*>(g_v + base + half * 32);
            #pragma unroll
            for (int j4 = 0; j4 < 8; j4++) {
                gv4[j4] = make_float4(kvv[4 * j4], kvv[4 * j4 + 1],
                                      kvv[4 * j4 + 2], kvv[4 * j4 + 3]);
            }
            if (half == 0) g_ven[(b << 10) + t] = 0.16f * nvt;
        }
    }

    // ---- q projection ----------------------------------------------------
    if ((cta & 7) == 7 && tid < 64) {
        const float* ht = sm + OFF_HT;
        float a0 = 0.f, a1 = 0.f, a2 = 0.f, a3 = 0.f;
        #pragma unroll 8
        for (int k = 0; k < 64; k += 4) {
            a0 = fmaf(ht[(k + 0) * RP + 127], __ldg(qpW + (k + 0) * 64 + tid), a0);
            a1 = fmaf(ht[(k + 1) * RP + 127], __ldg(qpW + (k + 1) * 64 + tid), a1);
            a2 = fmaf(ht[(k + 2) * RP + 127], __ldg(qpW + (k + 2) * 64 + tid), a2);
            a3 = fmaf(ht[(k + 3) * RP + 127], __ldg(qpW + (k + 3) * 64 + tid), a3);
        }
        g_q[(b << 6) + tid] = (a0 + a1) + (a2 + a3);
    }
}

// ---------------------------------------------------------------------------
// Kernel 1b: adjacent-key dots  gamma[b][t] = kn_t . kn_{t+1}
// ---------------------------------------------------------------------------
__global__ __launch_bounds__(256, 1)
void k_gamma()
{
    const int idx = blockIdx.x * 256 + threadIdx.x;
    const int b = idx >> 10;
    const int t = idx & 1023;
    float g = 0.0f;
    if (t <= LM1 - 2) {
        const float4* a = reinterpret_cast<const float4*>(g_k + (((size_t)(b * LM1 + t)) << 6));
        const float4* c = a + 16;
        float s0 = 0.f, s1 = 0.f, s2 = 0.f, s3 = 0.f;
        #pragma unroll
        for (int k = 0; k < 16; k += 2) {
            float4 x0 = a[k],     y0 = c[k];
            float4 x1 = a[k + 1], y1 = c[k + 1];
            s0 = fmaf(x0.x, y0.x, fmaf(x0.y, y0.y, s0));
            s1 = fmaf(x0.z, y0.z, fmaf(x0.w, y0.w, s1));
            s2 = fmaf(x1.x, y1.x, fmaf(x1.y, y1.y, s2));
            s3 = fmaf(x1.z, y1.z, fmaf(x1.w, y1.w, s3));
        }
        g = (s0 + s1) + (s2 + s3);
    }
    g_gam[(b << 10) + t] = g;
}

// ---------------------------------------------------------------------------
// Kernel 2: gated fast-weight scan — 2 gates/round, 128 threads (4 warps).
// Thread (p, h): p = tid>>1 owns M row p; h = tid&1 owns columns h*32..h*32+31
// (16 float2). Pair lanes are ADJACENT -> cross-half dot combine is one
// shfl.xor(1) inside the warp. Gate reduction: 5-hop tree on 0.5*(d^2,e^2,ed)
// (halving compensates pair duplication exactly), 4 warp partials via smem,
// ONE barrier per 2 steps. Scalar gate resolution identical to R9.
// ---------------------------------------------------------------------------
__global__ __launch_bounds__(128, 1)
void k_scan(const float* __restrict__ rpW,
            const float* __restrict__ rpb,
            const float* __restrict__ outW,
            const float* __restrict__ outb,
            float* __restrict__ out)
{
    __shared__ float  sK[2 * CH][64];
    __shared__ float  sV[2 * CH][64];
    __shared__ float  sVen[2 * CH];
    __shared__ float  sGam[2 * CH];
    __shared__ float4 sred[2][4];     // (D,E,C,-) per warp, parity-buffered
    __shared__ float  sq[64];
    __shared__ float  sr[64];

    const int i = threadIdx.x;        // 0..127
    const int b = blockIdx.x;
    const int lane = i & 31, w = i >> 5;
    const int p = i >> 1;             // row 0..63
    const int h = i & 1;              // column half

    const size_t base = (size_t)b * LM1 * 64;
    const int vb = b << 10;

    const uint32_t aK   = (uint32_t)__cvta_generic_to_shared(&sK[0][0]);
    const uint32_t aV   = (uint32_t)__cvta_generic_to_shared(&sV[0][0]);
    const uint32_t aVen = (uint32_t)__cvta_generic_to_shared(&sVen[0]);
    const uint32_t aGam = (uint32_t)__cvta_generic_to_shared(&sGam[0]);

    auto stage = [&](int q) {
        const int hb = (q & 1) * (CH * 64 * 4);
        const int hs = (q & 1) * (CH * 4);
        const char* gk = (const char*)(g_k + base) + ((size_t)q << 13);
        const char* gv = (const char*)(g_v + base) + ((size_t)q << 13);
        #pragma unroll
        for (int r = 0; r < 4; r++) {
            cp16(aK + hb + i * 16 + r * 2048, gk + i * 16 + r * 2048);
            cp16(aV + hb + i * 16 + r * 2048, gv + i * 16 + r * 2048);
        }
        if (i < 8) {
            cp16(aVen + hs + i * 16, (const char*)(g_ven + vb + q * CH) + i * 16);
        } else if (i < 16) {
            cp16(aGam + hs + (i - 8) * 16, (const char*)(g_gam + vb + q * CH) + (i - 8) * 16);
        }
        asm volatile("cp.async.commit_group;" ::: "memory");
    };

    // M half-row: columns h*32 + [0..31] as 16 float2
    float2 M[16];
    #pragma unroll
    for (int c = 0; c < 16; c++) M[c] = make_float2(0.f, 0.f);

    stage(0);
    asm volatile("cp.async.wait_group 0;" ::: "memory");
    __syncthreads();

    // ---- peel step 0: M=0 -> d_0 = v_0 -----------------------------------
    float gdA = 0.0f, gdB;
    {
        const float d = sV[0][p];               // both lanes of pair: same d
        float D = 0.5f * d * d;
        #pragma unroll
        for (int o = 1; o <= 16; o <<= 1) D += __shfl_xor_sync(0xffffffffu, D, o);
        if (lane == 0) sred[1][w] = make_float4(D, 0.f, 0.f, 0.f);
        __syncthreads();
        const float Dt = ((sred[1][0].x + sred[1][1].x) + (sred[1][2].x + sred[1][3].x));
        gdB = (Dt > sVen[0]) ? d : 0.0f;
    }

    // ---- main loop: 511 blocks of 2 steps, t = 1,3,...,1021 ---------------
    for (int j = 0; j < 511; j++) {
        const int t = 2 * j + 1;
        const int u = t + 1;
        const int ph = t & 31;
        if (ph == 3) {
            const int qn = (t >> 5) + 1;
            if (qn < 32) stage(qn);
        }
        if (ph == 31) {
            asm volatile("cp.async.wait_group 0;" ::: "memory");
            __syncthreads();
        }

        const int sA = (j == 0) ? 0 : ((t - 2) & 63);
        const int sB = (t - 1) & 63;
        const int sT = t & 63;
        const int sU = u & 63;

        // ---- batch: apply both pending updates -> M_{t-1} ----------------
        {
            const float4* kA = reinterpret_cast<const float4*>(sK[sA]) + h * 8;
            const float4* kB = reinterpret_cast<const float4*>(sK[sB]) + h * 8;
            const float2 ga = make_float2(gdA, gdA);
            const float2 gb = make_float2(gdB, gdB);
            #pragma unroll
            for (int c4 = 0; c4 < 8; c4++) {
                const float4 a = kA[c4];
                const float4 bq = kB[c4];
                float2 m0 = M[2 * c4], m1 = M[2 * c4 + 1];
                m0 = fma2(ga, make_float2(a.x, a.y), m0);
                m1 = fma2(ga, make_float2(a.z, a.w), m1);
                m0 = fma2(gb, make_float2(bq.x, bq.y), m0);
                m1 = fma2(gb, make_float2(bq.z, bq.w), m1);
                M[2 * c4] = m0; M[2 * c4 + 1] = m1;
            }
        }

        // ---- two half-matvecs with M_{t-1}; cross-half combine via shfl --
        float dt, eu;
        {
            const float4* kT = reinterpret_cast<const float4*>(sK[sT]) + h * 8;
            const float4* kU = reinterpret_cast<const float4*>(sK[sU]) + h * 8;
            float2 pt0 = make_float2(0.f, 0.f), pt1 = pt0;
            float2 pu0 = pt0, pu1 = pt0;
            #pragma unroll
            for (int c4 = 0; c4 < 8; c4 += 2) {
                const float4 a = kT[c4];
                const float4 bq = kT[c4 + 1];
                pt0 = fma2(M[2 * c4],     make_float2(a.x, a.y),  pt0);
                pt1 = fma2(M[2 * c4 + 1], make_float2(a.z, a.w),  pt1);
                pt0 = fma2(M[2 * c4 + 2], make_float2(bq.x, bq.y), pt0);
                pt1 = fma2(M[2 * c4 + 3], make_float2(bq.z, bq.w), pt1);
                const float4 a2 = kU[c4];
                const float4 b2 = kU[c4 + 1];
                pu0 = fma2(M[2 * c4],     make_float2(a2.x, a2.y), pu0);
                pu1 = fma2(M[2 * c4 + 1], make_float2(a2.z, a2.w), pu1);
                pu0 = fma2(M[2 * c4 + 2], make_float2(b2.x, b2.y), pu0);
                pu1 = fma2(M[2 * c4 + 3], make_float2(b2.z, b2.w), pu1);
            }
            float pt = (pt0.x + pt0.y) + (pt1.x + pt1.y);
            float pu = (pu0.x + pu0.y) + (pu1.x + pu1.y);
            const float ptx = __shfl_xor_sync(0xffffffffu, pt, 1);
            const float pux = __shfl_xor_sync(0xffffffffu, pu, 1);
            dt = sV[sT][p] - (pt + ptx);        // bit-identical across the pair
            eu = sV[sU][p] - (pu + pux);
        }

        // ---- one reduction round (0.5x compensates pair duplication) -----
        float D = 0.5f * dt * dt;
        float E = 0.5f * eu * eu;
        float C = 0.5f * eu * dt;
        #pragma unroll
        for (int o = 1; o <= 16; o <<= 1) {
            D += __shfl_xor_sync(0xffffffffu, D, o);
            E += __shfl_xor_sync(0xffffffffu, E, o);
            C += __shfl_xor_sync(0xffffffffu, C, o);
        }
        const int pb = j & 1;
        if (lane == 0) sred[pb][w] = make_float4(D, E, C, 0.f);
        __syncthreads();                      // the ONLY barrier per 2 steps
        const float4 r0 = sred[pb][0];
        const float4 r1 = sred[pb][1];
        const float4 r2 = sred[pb][2];
        const float4 r3 = sred[pb][3];
        const float Dt = (r0.x + r1.x) + (r2.x + r3.x);
        const float Et = (r0.y + r1.y) + (r2.y + r3.y);
        const float Ct = (r0.z + r1.z) + (r2.z + r3.z);

        // ---- resolve both gates scalar-side ------------------------------
        const float gam = sGam[sT];
        const bool gt = Dt > sVen[sT];
        const float a = gt ? gam : 0.0f;
        const float z2 = fmaf(a, fmaf(gam, Dt, -2.0f * Ct), Et);
        const bool gu = z2 > sVen[sU];
        gdA = gt ? dt : 0.0f;
        const float du = fmaf(-a, dt, eu);
        gdB = gu ? du : 0.0f;
    }

    // ---- final pending updates (steps 1021, 1022) ------------------------
    {
        const float4* kA = reinterpret_cast<const float4*>(sK[1021 & 63]) + h * 8;
        const float4* kB = reinterpret_cast<const float4*>(sK[1022 & 63]) + h * 8;
        const float2 ga = make_float2(gdA, gdA);
        const float2 gb = make_float2(gdB, gdB);
        #pragma unroll
        for (int c4 = 0; c4 < 8; c4++) {
            const float4 a = kA[c4];
            const float4 bq = kB[c4];
            float2 m0 = M[2 * c4], m1 = M[2 * c4 + 1];
            m0 = fma2(ga, make_float2(a.x, a.y), m0);
            m1 = fma2(ga, make_float2(a.z, a.w), m1);
            m0 = fma2(gb, make_float2(bq.x, bq.y), m0);
            m1 = fma2(gb, make_float2(bq.z, bq.w), m1);
            M[2 * c4] = m0; M[2 * c4 + 1] = m1;
        }
    }

    // -------- epilogue ----------------------------------------------------
    __syncthreads();
    if (i < 64) sq[i] = g_q[(b << 6) + i];
    __syncthreads();
    {
        const float4* qp = reinterpret_cast<const float4*>(sq) + h * 8;
        float2 p0 = make_float2(0.f, 0.f), p1 = p0;
        #pragma unroll
        for (int c4 = 0; c4 < 8; c4 += 2) {
            const float4 wa = qp[c4];
            const float4 wb = qp[c4 + 1];
            p0 = fma2(M[2 * c4],     make_float2(wa.x, wa.y), p0);
            p1 = fma2(M[2 * c4 + 1], make_float2(wa.z, wa.w), p1);
            p0 = fma2(M[2 * c4 + 2], make_float2(wb.x, wb.y), p0);
            p1 = fma2(M[2 * c4 + 3], make_float2(wb.z, wb.w), p1);
        }
        float mq = (p0.x + p0.y) + (p1.x + p1.y);
        mq += __shfl_xor_sync(0xffffffffu, mq, 1);
        if (h == 0) sr[p] = mq;
    }
    __syncthreads();
    if (i < 64) {
        float r = rpb[i];
        for (int jj = 0; jj < 64; jj++) r = fmaf(sr[jj], rpW[jj * 64 + i], r);
        __syncwarp(0xffffffffu);
        sq[i] = r;                      // reuse sq as staging for r
    }
    __syncthreads();
    if (i < 64) {
        float o = outb[i];
        for (int jj = 0; jj < 64; jj++) o = fmaf(sq[jj], outW[jj * 64 + i], o);
        out[(b << 6) + i] = o;
    }
}

// ---------------------------------------------------------------------------
extern "C" void kernel_launch(void* const* d_in, const int* in_sizes, int n_in,
                              void* d_out, int out_size)
{
    const int*   seq    = (const int*)  d_in[0];
    const float* embedW = (const float*)d_in[1];
    const float* W1     = (const float*)d_in[2];
    const float* b1     = (const float*)d_in[3];
    const float* W2     = (const float*)d_in[4];
    const float* b2     = (const float*)d_in[5];
    const float* lng    = (const float*)d_in[6];
    const float* lnb    = (const float*)d_in[7];
    const float* kpW    = (const float*)d_in[8];
    const float* vpW    = (const float*)d_in[9];
    const float* qpW    = (const float*)d_in[10];
    const float* rpW    = (const float*)d_in[11];
    const float* rpb    = (const float*)d_in[12];
    const float* outW   = (const float*)d_in[13];
    const float* outb   = (const float*)d_in[14];
    float* out = (float*)d_out;

    const int smem = SMEM_TOK_FLOATS * (int)sizeof(float);   // 201984 B
    cudaFuncSetAttribute(k_tokens, cudaFuncAttributeMaxDynamicSharedMemorySize, smem);

    k_tokens<<<512, 256, smem>>>(seq, embedW, W1, b1, W2, b2, lng, lnb, kpW, vpW, qpW);
    k_gamma<<<256, 256>>>();
    k_scan<<<64, 128>>>(rpW, rpb, outW, outb, out);
}

// round 11
// speedup vs baseline: 1.0391x; 1.0391x over previous
#include <cuda_runtime.h>
#include <cstdint>
#include <cstddef>

#define BB 64
#define LL 1024
#define HH 64
#define LM1 1023
#define CH 32            // scan staging chunk (steps)
#define TPC 128          // tokens per CTA in k_tokens
#define RP 132           // padded row length (floats) for transposed smem tiles

// Scratch (device globals — the allowed scratch mechanism). Zero-initialized.
__device__ float g_k   [BB * LM1 * HH + 4 * HH];  // pre-normalized keys (padding for gamma reads)
__device__ float g_v   [BB * LM1 * HH + 2 * HH];  // values
__device__ float g_ven [BB * 1024];               // 0.16*||v||^2
__device__ float g_gam1[BB * 1024];               // <kn_t, kn_{t+1}>
__device__ float g_gam2[BB * 1024];               // <kn_t, kn_{t+2}>
__device__ float g_gam3[BB * 1024];               // <kn_t, kn_{t+3}>
__device__ float g_q   [BB * HH];

// Packed f32x2 FMA
__device__ __forceinline__ float2 fma2(float2 a, float2 b, float2 c) {
    float2 d;
    asm("fma.rn.f32x2 %0, %1, %2, %3;"
        : "=l"(*reinterpret_cast<unsigned long long*>(&d))
        : "l"(*reinterpret_cast<unsigned long long*>(&a)),
          "l"(*reinterpret_cast<unsigned long long*>(&b)),
          "l"(*reinterpret_cast<unsigned long long*>(&c)));
    return d;
}

__device__ __forceinline__ void cp16(uint32_t dst, const void* src) {
    asm volatile("cp.async.cg.shared.global [%0], [%1], 16;" :: "r"(dst), "l"(src));
}

// Shared-memory float offsets for k_tokens (total 50496 floats = 197.25 KB)
#define OFF_WA   0
#define OFF_WB   8192
#define OFF_HT   16384
#define OFF_ST   24832
#define OFF_FFT  41728
#define OFF_B1   50176
#define OFF_B2   50304
#define OFF_G    50368
#define OFF_BT   50432
#define SMEM_TOK_FLOATS 50496

// ---------------------------------------------------------------------------
// Kernel 1: cooperative register-tiled GEMM pipeline (unchanged from R8).
// ---------------------------------------------------------------------------
__global__ __launch_bounds__(256, 1)
void k_tokens(const int*   __restrict__ seq,
              const float* __restrict__ embedW,
              const float* __restrict__ W1,
              const float* __restrict__ b1,
              const float* __restrict__ W2,
              const float* __restrict__ b2,
              const float* __restrict__ lng,
              const float* __restrict__ lnb,
              const float* __restrict__ kpW,
              const float* __restrict__ vpW,
              const float* __restrict__ qpW)
{
    extern __shared__ float sm[];
    const int tid = threadIdx.x;
    const int cta = blockIdx.x;
    const int b = cta >> 3;
    const int tbase = (cta & 7) * TPC;

    const uint32_t smA = (uint32_t)__cvta_generic_to_shared(sm + OFF_WA);
    const uint32_t smB = (uint32_t)__cvta_generic_to_shared(sm + OFF_WB);

    #pragma unroll
    for (int r = 0; r < 8; r++) {
        cp16(smA + (tid + 256 * r) * 16, (const char*)W1 + (tid + 256 * r) * 16);
        cp16(smB + (tid + 256 * r) * 16, (const char*)W2 + (tid + 256 * r) * 16);
    }
    asm volatile("cp.async.commit_group;" ::: "memory");

    if (tid < 128) sm[OFF_B1 + tid] = b1[tid];
    if (tid < 64) {
        sm[OFF_B2 + tid] = b2[tid];
        sm[OFF_G  + tid] = lng[tid];
        sm[OFF_BT + tid] = lnb[tid];
    }

    const int tok  = tid >> 1;
    const int half = tid & 1;
    {
        const int sidx = seq[(b << 10) + tbase + tok];
        const float4* e4 = reinterpret_cast<const float4*>(embedW + (sidx << 6) + half * 32);
        float* ht = sm + OFF_HT;
        #pragma unroll
        for (int r = 0; r < 8; r++) {
            float4 w = e4[r];
            int k = half * 32 + r * 4;
            ht[(k + 0) * RP + tok] = w.x;
            ht[(k + 1) * RP + tok] = w.y;
            ht[(k + 2) * RP + tok] = w.z;
            ht[(k + 3) * RP + tok] = w.w;
        }
    }
    asm volatile("cp.async.wait_group 0;" ::: "memory");
    __syncthreads();

    // ---- GEMM1 -----------------------------------------------------------
    {
        const int m0 = (tid & 15) * 8;
        const int n0 = (tid >> 4) * 8;
        float2 c1[8][4];
        #pragma unroll
        for (int ni = 0; ni < 8; ni++)
            #pragma unroll
            for (int mj = 0; mj < 4; mj++) c1[ni][mj] = make_float2(0.f, 0.f);

        const float4* ht4 = reinterpret_cast<const float4*>(sm + OFF_HT);
        const float4* w14 = reinterpret_cast<const float4*>(sm + OFF_WA);
        #pragma unroll 4
        for (int k = 0; k < 64; k++) {
            const float4 a0 = ht4[k * (RP / 4) + m0 / 4];
            const float4 a1 = ht4[k * (RP / 4) + m0 / 4 + 1];
            const float2 am[4] = { {a0.x, a0.y}, {a0.z, a0.w}, {a1.x, a1.y}, {a1.z, a1.w} };
            const float4 b0 = w14[k * 32 + n0 / 4];
            const float4 bq = w14[k * 32 + n0 / 4 + 1];
            const float bn[8] = { b0.x, b0.y, b0.z, b0.w, bq.x, bq.y, bq.z, bq.w };
            #pragma unroll
            for (int ni = 0; ni < 8; ni++) {
                const float2 bb = make_float2(bn[ni], bn[ni]);
                #pragma unroll
                for (int mj = 0; mj < 4; mj++)
                    c1[ni][mj] = fma2(bb, am[mj], c1[ni][mj]);
            }
        }
        float4* st4 = reinterpret_cast<float4*>(sm + OFF_ST);
        #pragma unroll
        for (int ni = 0; ni < 8; ni++) {
            const float bb = sm[OFF_B1 + n0 + ni];
            float2 r0 = c1[ni][0], r1 = c1[ni][1], r2 = c1[ni][2], r3 = c1[ni][3];
            r0.x = fmaxf(r0.x + bb, 0.f); r0.y = fmaxf(r0.y + bb, 0.f);
            r1.x = fmaxf(r1.x + bb, 0.f); r1.y = fmaxf(r1.y + bb, 0.f);
            r2.x = fmaxf(r2.x + bb, 0.f); r2.y = fmaxf(r2.y + bb, 0.f);
            r3.x = fmaxf(r3.x + bb, 0.f); r3.y = fmaxf(r3.y + bb, 0.f);
            st4[(n0 + ni) * (RP / 4) + m0 / 4]     = make_float4(r0.x, r0.y, r1.x, r1.y);
            st4[(n0 + ni) * (RP / 4) + m0 / 4 + 1] = make_float4(r2.x, r2.y, r3.x, r3.y);
        }
    }
    __syncthreads();

    // ---- prefetch KV-combined weights [64][128] (2048 float4s) -----------
    {
        #pragma unroll
        for (int r = 0; r < 8; r++) {
            const int f = tid + 256 * r;
            const int k = f >> 5;
            const int c4 = f & 31;
            const char* src = (c4 < 16)
                ? (const char*)kpW + (k * 16 + c4) * 16
                : (const char*)vpW + (k * 16 + (c4 - 16)) * 16;
            cp16(smA + f * 16, src);
        }
        asm volatile("cp.async.commit_group;" ::: "memory");
    }

    // ---- GEMM2 -----------------------------------------------------------
    {
        const int m0 = (tid >> 4) * 8;
        const int n0 = (tid & 15) * 4;
        float2 c2[4][4];
        #pragma unroll
        for (int ni = 0; ni < 4; ni++)
            #pragma unroll
            for (int mj = 0; mj < 4; mj++) c2[ni][mj] = make_float2(0.f, 0.f);

        const float4* st4 = reinterpret_cast<const float4*>(sm + OFF_ST);
        const float4* w24 = reinterpret_cast<const float4*>(sm + OFF_WB);
        #pragma unroll 4
        for (int k = 0; k < 128; k++) {
            const float4 a0 = st4[k * (RP / 4) + m0 / 4];
            const float4 a1 = st4[k * (RP / 4) + m0 / 4 + 1];
            const float2 am[4] = { {a0.x, a0.y}, {a0.z, a0.w}, {a1.x, a1.y}, {a1.z, a1.w} };
            const float4 b0 = w24[k * 16 + n0 / 4];
            const float bn[4] = { b0.x, b0.y, b0.z, b0.w };
            #pragma unroll
            for (int ni = 0; ni < 4; ni++) {
                const float2 bb = make_float2(bn[ni], bn[ni]);
                #pragma unroll
                for (int mj = 0; mj < 4; mj++)
                    c2[ni][mj] = fma2(bb, am[mj], c2[ni][mj]);
            }
        }
        float4* ff4 = reinterpret_cast<float4*>(sm + OFF_FFT);
        #pragma unroll
        for (int ni = 0; ni < 4; ni++) {
            const float bb = sm[OFF_B2 + n0 + ni];
            float2 r0 = c2[ni][0], r1 = c2[ni][1], r2 = c2[ni][2], r3 = c2[ni][3];
            r0.x += bb; r0.y += bb; r1.x += bb; r1.y += bb;
            r2.x += bb; r2.y += bb; r3.x += bb; r3.y += bb;
            ff4[(n0 + ni) * (RP / 4) + m0 / 4]     = make_float4(r0.x, r0.y, r1.x, r1.y);
            ff4[(n0 + ni) * (RP / 4) + m0 / 4 + 1] = make_float4(r2.x, r2.y, r3.x, r3.y);
        }
    }
    __syncthreads();

    // ---- LayerNorm per token ---------------------------------------------
    {
        float x[32];
        const float* ht = sm + OFF_HT;
        const float* ff = sm + OFF_FFT;
        #pragma unroll
        for (int j = 0; j < 32; j++) {
            const int k = half * 32 + j;
            x[j] = ht[k * RP + tok] + ff[k * RP + tok];
        }
        float s1 = 0.f;
        #pragma unroll
        for (int j = 0; j < 32; j++) s1 += x[j];
        s1 += __shfl_xor_sync(0xffffffffu, s1, 1);
        const float mu = s1 * (1.0f / 64.0f);
        float s2 = 0.f;
        #pragma unroll
        for (int j = 0; j < 32; j++) { const float dx = x[j] - mu; s2 += dx * dx; }
        s2 += __shfl_xor_sync(0xffffffffu, s2, 1);
        const float inv = 1.0f / sqrtf(s2 * (1.0f / 64.0f) + 1e-5f);
        float* hw = sm + OFF_HT;
        #pragma unroll
        for (int j = 0; j < 32; j++) {
            const int k = half * 32 + j;
            hw[k * RP + tok] = (x[j] - mu) * inv * sm[OFF_G + k] + sm[OFF_BT + k];
        }
    }
    asm volatile("cp.async.wait_group 0;" ::: "memory");
    __syncthreads();

    // ---- GEMM3: K|V ------------------------------------------------------
    {
        const int m0 = (tid & 15) * 8;
        const int n0 = (tid >> 4) * 8;
        float2 c3[8][4];
        #pragma unroll
        for (int ni = 0; ni < 8; ni++)
            #pragma unroll
            for (int mj = 0; mj < 4; mj++) c3[ni][mj] = make_float2(0.f, 0.f);

        const float4* ht4 = reinterpret_cast<const float4*>(sm + OFF_HT);
        const float4* wk4 = reinterpret_cast<const float4*>(sm + OFF_WA);
        #pragma unroll 4
        for (int k = 0; k < 64; k++) {
            const float4 a0 = ht4[k * (RP / 4) + m0 / 4];
            const float4 a1 = ht4[k * (RP / 4) + m0 / 4 + 1];
            const float2 am[4] = { {a0.x, a0.y}, {a0.z, a0.w}, {a1.x, a1.y}, {a1.z, a1.w} };
            const float4 b0 = wk4[k * 32 + n0 / 4];
            const float4 bq = wk4[k * 32 + n0 / 4 + 1];
            const float bn[8] = { b0.x, b0.y, b0.z, b0.w, bq.x, bq.y, bq.z, bq.w };
            #pragma unroll
            for (int ni = 0; ni < 8; ni++) {
                const float2 bb = make_float2(bn[ni], bn[ni]);
                #pragma unroll
                for (int mj = 0; mj < 4; mj++)
                    c3[ni][mj] = fma2(bb, am[mj], c3[ni][mj]);
            }
        }
        float4* kv4 = reinterpret_cast<float4*>(sm + OFF_ST);
        #pragma unroll
        for (int ni = 0; ni < 8; ni++) {
            const float2 r0 = c3[ni][0], r1 = c3[ni][1], r2 = c3[ni][2], r3 = c3[ni][3];
            kv4[(n0 + ni) * (RP / 4) + m0 / 4]     = make_float4(r0.x, r0.y, r1.x, r1.y);
            kv4[(n0 + ni) * (RP / 4) + m0 / 4 + 1] = make_float4(r2.x, r2.y, r3.x, r3.y);
        }
    }
    __syncthreads();

    // ---- k-normalize, ven, stores ----------------------------------------
    {
        const int t = tbase + tok;
        const float* kv = sm + OFF_ST;
        float kvv[32];
        float nk = 0.f;
        #pragma unroll
        for (int j = 0; j < 32; j++) {
            kvv[j] = kv[(half * 32 + j) * RP + tok];
            nk = fmaf(kvv[j], kvv[j], nk);
        }
        nk += __shfl_xor_sync(0xffffffffu, nk, 1);
        const float kinv = 1.0f / fmaxf(sqrtf(nk), 1e-12f);
        if (t < LM1) {
            const size_t base = ((size_t)(b * LM1 + t)) << 6;
            float4* gk4 = reinterpret_cast<float4*>(g_k + base + half * 32);
            #pragma unroll
            for (int j4 = 0; j4 < 8; j4++) {
                gk4[j4] = make_float4(kvv[4 * j4] * kinv, kvv[4 * j4 + 1] * kinv,
                                      kvv[4 * j4 + 2] * kinv, kvv[4 * j4 + 3] * kinv);
            }
        }
        float nv = 0.f;
        #pragma unroll
        for (int j = 0; j < 32; j++) {
            kvv[j] = kv[(64 + half * 32 + j) * RP + tok];
            nv = fmaf(kvv[j], kvv[j], nv);
        }
        const float nvt = nv + __shfl_xor_sync(0xffffffffu, nv, 1);
        if (t < LM1) {
            const size_t base = ((size_t)(b * LM1 + t)) << 6;
            float4* gv4 = reinterpret_cast<float4*>(g_v + base + half * 32);
            #pragma unroll
            for (int j4 = 0; j4 < 8; j4++) {
                gv4[j4] = make_float4(kvv[4 * j4], kvv[4 * j4 + 1],
                                      kvv[4 * j4 + 2], kvv[4 * j4 + 3]);
            }
            if (half == 0) g_ven[(b << 10) + t] = 0.16f * nvt;
        }
    }

    // ---- q projection ----------------------------------------------------
    if ((cta & 7) == 7 && tid < 64) {
        const float* ht = sm + OFF_HT;
        float a0 = 0.f, a1 = 0.f, a2 = 0.f, a3 = 0.f;
        #pragma unroll 8
        for (int k = 0; k < 64; k += 4) {
            a0 = fmaf(ht[(k + 0) * RP + 127], __ldg(qpW + (k + 0) * 64 + tid), a0);
            a1 = fmaf(ht[(k + 1) * RP + 127], __ldg(qpW + (k + 1) * 64 + tid), a1);
            a2 = fmaf(ht[(k + 2) * RP + 127], __ldg(qpW + (k + 2) * 64 + tid), a2);
            a3 = fmaf(ht[(k + 3) * RP + 127], __ldg(qpW + (k + 3) * 64 + tid), a3);
        }
        g_q[(b << 6) + tid] = (a0 + a1) + (a2 + a3);
    }
}

// ---------------------------------------------------------------------------
// Kernel 1b: key Gram at distances 1..3.
// ---------------------------------------------------------------------------
__global__ __launch_bounds__(256, 1)
void k_gamma()
{
    const int idx = blockIdx.x * 256 + threadIdx.x;
    const int b = idx >> 10;
    const int t = idx & 1023;
    float d1 = 0.f, d2 = 0.f, d3 = 0.f;
    if (t <= 1022) {
        const float4* a = reinterpret_cast<const float4*>(g_k + (((size_t)(b * LM1 + t)) << 6));
        #pragma unroll
        for (int k = 0; k < 16; k++) {
            const float4 x = a[k];
            const float4 y1 = a[k + 16];
            const float4 y2 = a[k + 32];
            const float4 y3 = a[k + 48];
            d1 = fmaf(x.x, y1.x, fmaf(x.y, y1.y, fmaf(x.z, y1.z, fmaf(x.w, y1.w, d1))));
            d2 = fmaf(x.x, y2.x, fmaf(x.y, y2.y, fmaf(x.z, y2.z, fmaf(x.w, y2.w, d2))));
            d3 = fmaf(x.x, y3.x, fmaf(x.y, y3.y, fmaf(x.z, y3.z, fmaf(x.w, y3.w, d3))));
        }
    }
    g_gam1[(b << 10) + t] = (t <= 1021) ? d1 : 0.f;
    g_gam2[(b << 10) + t] = (t <= 1020) ? d2 : 0.f;
    g_gam3[(b << 10) + t] = (t <= 1019) ? d3 : 0.f;
}

// ---------------------------------------------------------------------------
// Kernel 2: gated fast-weight scan — 4 gates per serial round, 128 threads.
// Thread (p, h): row p = i>>1, column half h = i&1 (16 float2 of M).
// Per block (t..t+3): apply 4 pending rank-1 updates -> M_{t-1};
//   e_m = v_{t+m} - M_{t-1} kn_{t+m} (half-dots + pair shfl combine);
//   reduce E[m][n] (10 scalars, one tree + ONE barrier);
//   resolve gates g_0..g_3 scalar-side with precomputed key Gram G1/G2/G3;
//   per-component d_m = e_m - sum c_im d_i (exact M path); stash pending gd.
// ---------------------------------------------------------------------------
__global__ __launch_bounds__(128, 1)
void k_scan(const float* __restrict__ rpW,
            const float* __restrict__ rpb,
            const float* __restrict__ outW,
            const float* __restrict__ outb,
            float* __restrict__ out)
{
    __shared__ float  sK[2 * CH][64];
    __shared__ float  sV[2 * CH][64];
    __shared__ float  sVen[2 * CH];
    __shared__ float  sG1[2 * CH];
    __shared__ float  sG2[2 * CH];
    __shared__ float  sG3[2 * CH];
    __shared__ float4 sred[4];          // 3-value rounds (peel/tail)
    __shared__ float  sredE[4][12];     // 10 E-partials per warp (padded)
    __shared__ float  sq[64];
    __shared__ float  sr[64];

    const int i = threadIdx.x;
    const int b = blockIdx.x;
    const int lane = i & 31, w = i >> 5;
    const int p = i >> 1;
    const int h = i & 1;

    const size_t base = (size_t)b * LM1 * 64;
    const int vb = b << 10;

    const uint32_t aK   = (uint32_t)__cvta_generic_to_shared(&sK[0][0]);
    const uint32_t aV   = (uint32_t)__cvta_generic_to_shared(&sV[0][0]);
    const uint32_t aVen = (uint32_t)__cvta_generic_to_shared(&sVen[0]);
    const uint32_t aG1  = (uint32_t)__cvta_generic_to_shared(&sG1[0]);
    const uint32_t aG2  = (uint32_t)__cvta_generic_to_shared(&sG2[0]);
    const uint32_t aG3  = (uint32_t)__cvta_generic_to_shared(&sG3[0]);

    auto stage = [&](int q) {
        const int hb = (q & 1) * (CH * 64 * 4);
        const int hs = (q & 1) * (CH * 4);
        const char* gk = (const char*)(g_k + base) + ((size_t)q << 13);
        const char* gv = (const char*)(g_v + base) + ((size_t)q << 13);
        #pragma unroll
        for (int r = 0; r < 4; r++) {
            cp16(aK + hb + i * 16 + r * 2048, gk + i * 16 + r * 2048);
            cp16(aV + hb + i * 16 + r * 2048, gv + i * 16 + r * 2048);
        }
        if (i < 8)       cp16(aVen + hs + i * 16,        (const char*)(g_ven  + vb + q * CH) + i * 16);
        else if (i < 16) cp16(aG1  + hs + (i - 8) * 16,  (const char*)(g_gam1 + vb + q * CH) + (i - 8) * 16);
        else if (i < 24) cp16(aG2  + hs + (i - 16) * 16, (const char*)(g_gam2 + vb + q * CH) + (i - 16) * 16);
        else if (i < 32) cp16(aG3  + hs + (i - 24) * 16, (const char*)(g_gam3 + vb + q * CH) + (i - 24) * 16);
        asm volatile("cp.async.commit_group;" ::: "memory");
    };

    float2 M[16];     // M[p][h*32 + 0..31]
    #pragma unroll
    for (int c = 0; c < 16; c++) M[c] = make_float2(0.f, 0.f);

    stage(0);
    asm volatile("cp.async.wait_group 0;" ::: "memory");
    __syncthreads();

    // ---- peel step 0: M=0 -> d_0 = v_0 -----------------------------------
    float gdP0 = 0.f, gdP1 = 0.f, gdP2 = 0.f, gdP3;
    {
        const float d = sV[0][p];
        float D = 0.5f * d * d;
        #pragma unroll
        for (int o = 1; o <= 16; o <<= 1) D += __shfl_xor_sync(0xffffffffu, D, o);
        if (lane == 0) sred[w] = make_float4(D, 0.f, 0.f, 0.f);
        __syncthreads();
        const float Dt = (sred[0].x + sred[1].x) + (sred[2].x + sred[3].x);
        gdP3 = (Dt > sVen[0]) ? d : 0.0f;
    }

    // ---- main loop: 255 blocks of 4 steps, t = 1,5,...,1017 ---------------
    for (int j = 0; j < 255; j++) {
        const int t = 4 * j + 1;
        const int ph = t & 31;
        if (ph == 5) {
            const int qn = (t >> 5) + 1;
            if (qn < 32) stage(qn);
        }
        if (ph == 29) {                       // block reads t+3 in new chunk
            asm volatile("cp.async.wait_group 0;" ::: "memory");
            __syncthreads();
        }

        // pending-update key slots (t-4..t-1); clamp for j==0 (gd==0 there)
        const int sp0 = (t >= 4) ? ((t - 4) & 63) : 0;
        const int sp1 = (t >= 3) ? ((t - 3) & 63) : 0;
        const int sp2 = (t >= 2) ? ((t - 2) & 63) : 0;
        const int sp3 = (t - 1) & 63;
        const int sT0 = t & 63, sT1 = (t + 1) & 63, sT2 = (t + 2) & 63, sT3 = (t + 3) & 63;

        // ---- batch 1: apply 4 pending updates -> M_{t-1} -----------------
        {
            const float4* k0 = reinterpret_cast<const float4*>(sK[sp0]) + h * 8;
            const float4* k1 = reinterpret_cast<const float4*>(sK[sp1]) + h * 8;
            const float4* k2 = reinterpret_cast<const float4*>(sK[sp2]) + h * 8;
            const float4* k3 = reinterpret_cast<const float4*>(sK[sp3]) + h * 8;
            const float2 g0 = make_float2(gdP0, gdP0);
            const float2 g1 = make_float2(gdP1, gdP1);
            const float2 g2 = make_float2(gdP2, gdP2);
            const float2 g3 = make_float2(gdP3, gdP3);
            #pragma unroll
            for (int c4 = 0; c4 < 8; c4++) {
                const float4 a0 = k0[c4];
                const float4 a1 = k1[c4];
                const float4 a2 = k2[c4];
                const float4 a3 = k3[c4];
                float2 m0 = M[2 * c4], m1 = M[2 * c4 + 1];
                m0 = fma2(g0, make_float2(a0.x, a0.y), m0);
                m1 = fma2(g0, make_float2(a0.z, a0.w), m1);
                m0 = fma2(g1, make_float2(a1.x, a1.y), m0);
                m1 = fma2(g1, make_float2(a1.z, a1.w), m1);
                m0 = fma2(g2, make_float2(a2.x, a2.y), m0);
                m1 = fma2(g2, make_float2(a2.z, a2.w), m1);
                m0 = fma2(g3, make_float2(a3.x, a3.y), m0);
                m1 = fma2(g3, make_float2(a3.z, a3.w), m1);
                M[2 * c4] = m0; M[2 * c4 + 1] = m1;
            }
        }

        // ---- batch 2: four half-matvecs, pair combine --------------------
        float e0, e1, e2, e3;
        {
            const float4* k0 = reinterpret_cast<const float4*>(sK[sT0]) + h * 8;
            const float4* k1 = reinterpret_cast<const float4*>(sK[sT1]) + h * 8;
            const float4* k2 = reinterpret_cast<const float4*>(sK[sT2]) + h * 8;
            const float4* k3 = reinterpret_cast<const float4*>(sK[sT3]) + h * 8;
            float2 u0 = make_float2(0.f, 0.f), u1 = u0, u2 = u0, u3 = u0;
            #pragma unroll
            for (int c4 = 0; c4 < 8; c4++) {
                const float2 ma = M[2 * c4];
                const float2 mb = M[2 * c4 + 1];
                const float4 a0 = k0[c4];
                const float4 a1 = k1[c4];
                const float4 a2 = k2[c4];
                const float4 a3 = k3[c4];
                u0 = fma2(ma, make_float2(a0.x, a0.y), u0);
                u0 = fma2(mb, make_float2(a0.z, a0.w), u0);
                u1 = fma2(ma, make_float2(a1.x, a1.y), u1);
                u1 = fma2(mb, make_float2(a1.z, a1.w), u1);
                u2 = fma2(ma, make_float2(a2.x, a2.y), u2);
                u2 = fma2(mb, make_float2(a2.z, a2.w), u2);
                u3 = fma2(ma, make_float2(a3.x, a3.y), u3);
                u3 = fma2(mb, make_float2(a3.z, a3.w), u3);
            }
            float s0 = u0.x + u0.y, s1 = u1.x + u1.y, s2 = u2.x + u2.y, s3 = u3.x + u3.y;
            const float x0 = __shfl_xor_sync(0xffffffffu, s0, 1);
            const float x1 = __shfl_xor_sync(0xffffffffu, s1, 1);
            const float x2 = __shfl_xor_sync(0xffffffffu, s2, 1);
            const float x3 = __shfl_xor_sync(0xffffffffu, s3, 1);
            e0 = sV[sT0][p] - (s0 + x0);
            e1 = sV[sT1][p] - (s1 + x1);
            e2 = sV[sT2][p] - (s2 + x2);
            e3 = sV[sT3][p] - (s3 + x3);
        }

        // ---- reduction: E Gram (10 scalars), one tree, ONE barrier -------
        const float h0 = 0.5f * e0, h1 = 0.5f * e1, h2 = 0.5f * e2;
        float E00 = h0 * e0, E01 = h0 * e1, E02 = h0 * e2, E03 = h0 * e3;
        float E11 = h1 * e1, E12 = h1 * e2, E13 = h1 * e3;
        float E22 = h2 * e2, E23 = h2 * e3;
        float E33 = 0.5f * e3 * e3;
        #pragma unroll
        for (int o = 1; o <= 16; o <<= 1) {
            E00 += __shfl_xor_sync(0xffffffffu, E00, o);
            E01 += __shfl_xor_sync(0xffffffffu, E01, o);
            E02 += __shfl_xor_sync(0xffffffffu, E02, o);
            E03 += __shfl_xor_sync(0xffffffffu, E03, o);
            E11 += __shfl_xor_sync(0xffffffffu, E11, o);
            E12 += __shfl_xor_sync(0xffffffffu, E12, o);
            E13 += __shfl_xor_sync(0xffffffffu, E13, o);
            E22 += __shfl_xor_sync(0xffffffffu, E22, o);
            E23 += __shfl_xor_sync(0xffffffffu, E23, o);
            E33 += __shfl_xor_sync(0xffffffffu, E33, o);
        }
        if (lane == 0) {
            float* dst = sredE[w];
            dst[0] = E00; dst[1] = E01; dst[2] = E02; dst[3] = E03;
            dst[4] = E11; dst[5] = E12; dst[6] = E13; dst[7] = E22;
            dst[8] = E23; dst[9] = E33;
        }
        __syncthreads();                      // the ONLY barrier per 4 steps
        {
            const float4* r0 = reinterpret_cast<const float4*>(sredE[0]);
            const float4* r1 = reinterpret_cast<const float4*>(sredE[1]);
            const float4* r2 = reinterpret_cast<const float4*>(sredE[2]);
            const float4* r3 = reinterpret_cast<const float4*>(sredE[3]);
            const float4 a0 = r0[0], b0 = r1[0], c0 = r2[0], d0 = r3[0];
            const float4 a1 = r0[1], b1 = r1[1], c1 = r2[1], d1 = r3[1];
            const float4 a2 = r0[2], b2 = r1[2], c2 = r2[2], d2 = r3[2];
            E00 = (a0.x + b0.x) + (c0.x + d0.x);
            E01 = (a0.y + b0.y) + (c0.y + d0.y);
            E02 = (a0.z + b0.z) + (c0.z + d0.z);
            E03 = (a0.w + b0.w) + (c0.w + d0.w);
            E11 = (a1.x + b1.x) + (c1.x + d1.x);
            E12 = (a1.y + b1.y) + (c1.y + d1.y);
            E13 = (a1.z + b1.z) + (c1.z + d1.z);
            E22 = (a1.w + b1.w) + (c1.w + d1.w);
            E23 = (a2.x + b2.x) + (c2.x + d2.x);
            E33 = (a2.y + b2.y) + (c2.y + d2.y);
        }

        // ---- resolve 4 gates scalar-side ---------------------------------
        const float G01 = sG1[sT0], G12 = sG1[sT1], G23 = sG1[sT2];
        const float G02 = sG2[sT0], G13 = sG2[sT1], G03 = sG3[sT0];
        const float v0 = sVen[sT0], v1 = sVen[sT1], v2 = sVen[sT2], v3 = sVen[sT3];

        const bool g0 = E00 > v0;
        const float c01 = g0 ? G01 : 0.f, c02 = g0 ? G02 : 0.f, c03 = g0 ? G03 : 0.f;
        const float D1 = E11 - 2.f * c01 * E01 + c01 * c01 * E00;
        const bool g1 = D1 > v1;
        const float c12 = g1 ? G12 : 0.f, c13 = g1 ? G13 : 0.f;
        const float a20 = c12 * c01 - c02, a21 = -c12;
        const float D2 = a20 * a20 * E00 + a21 * a21 * E11 + E22
                       + 2.f * (a20 * a21 * E01 + a20 * E02 + a21 * E12);
        const bool g2 = D2 > v2;
        const float c23 = g2 ? G23 : 0.f;
        const float a30 = c13 * c01 - c03 - c23 * a20;
        const float a31 = -c13 - c23 * a21;
        const float a32 = -c23;
        const float D3 = a30 * a30 * E00 + a31 * a31 * E11 + a32 * a32 * E22 + E33
                       + 2.f * (a30 * a31 * E01 + a30 * a32 * E02 + a30 * E03
                              + a31 * a32 * E12 + a31 * E13 + a32 * E23);
        const bool g3 = D3 > v3;

        // ---- per-component d's (exact), stash pending gd -----------------
        const float d0c = e0;
        const float d1c = e1 - c01 * d0c;
        const float d2c = e2 - c02 * d0c - c12 * d1c;
        const float d3c = e3 - c03 * d0c - c13 * d1c - c23 * d2c;
        gdP0 = g0 ? d0c : 0.f;
        gdP1 = g1 ? d1c : 0.f;
        gdP2 = g2 ? d2c : 0.f;
        gdP3 = g3 ? d3c : 0.f;
    }

    // ---- tail: apply pending (1017..1020), then steps 1021,1022 ----------
    {
        const float4* k0 = reinterpret_cast<const float4*>(sK[1017 & 63]) + h * 8;
        const float4* k1 = reinterpret_cast<const float4*>(sK[1018 & 63]) + h * 8;
        const float4* k2 = reinterpret_cast<const float4*>(sK[1019 & 63]) + h * 8;
        const float4* k3 = reinterpret_cast<const float4*>(sK[1020 & 63]) + h * 8;
        const float2 g0 = make_float2(gdP0, gdP0);
        const float2 g1 = make_float2(gdP1, gdP1);
        const float2 g2 = make_float2(gdP2, gdP2);
        const float2 g3 = make_float2(gdP3, gdP3);
        #pragma unroll
        for (int c4 = 0; c4 < 8; c4++) {
            const float4 a0 = k0[c4];
            const float4 a1 = k1[c4];
            const float4 a2 = k2[c4];
            const float4 a3 = k3[c4];
            float2 m0 = M[2 * c4], m1 = M[2 * c4 + 1];
            m0 = fma2(g0, make_float2(a0.x, a0.y), m0);
            m1 = fma2(g0, make_float2(a0.z, a0.w), m1);
            m0 = fma2(g1, make_float2(a1.x, a1.y), m0);
            m1 = fma2(g1, make_float2(a1.z, a1.w), m1);
            m0 = fma2(g2, make_float2(a2.x, a2.y), m0);
            m1 = fma2(g2, make_float2(a2.z, a2.w), m1);
            m0 = fma2(g3, make_float2(a3.x, a3.y), m0);
            m1 = fma2(g3, make_float2(a3.z, a3.w), m1);
            M[2 * c4] = m0; M[2 * c4 + 1] = m1;
        }
    }
    {
        const int sT = 1021 & 63, sU = 1022 & 63;
        const float4* kT = reinterpret_cast<const float4*>(sK[sT]) + h * 8;
        const float4* kU = reinterpret_cast<const float4*>(sK[sU]) + h * 8;
        float2 ut = make_float2(0.f, 0.f), uu = ut;
        #pragma unroll
        for (int c4 = 0; c4 < 8; c4++) {
            const float2 ma = M[2 * c4];
            const float2 mb = M[2 * c4 + 1];
            const float4 aT = kT[c4];
            const float4 aU = kU[c4];
            ut = fma2(ma, make_float2(aT.x, aT.y), ut);
            ut = fma2(mb, make_float2(aT.z, aT.w), ut);
            uu = fma2(ma, make_float2(aU.x, aU.y), uu);
            uu = fma2(mb, make_float2(aU.z, aU.w), uu);
        }
        float st = ut.x + ut.y, su = uu.x + uu.y;
        const float xt = __shfl_xor_sync(0xffffffffu, st, 1);
        const float xu = __shfl_xor_sync(0xffffffffu, su, 1);
        const float dt = sV[sT][p] - (st + xt);
        const float eu = sV[sU][p] - (su + xu);

        float D = 0.5f * dt * dt;
        float E = 0.5f * eu * eu;
        float C = 0.5f * eu * dt;
        #pragma unroll
        for (int o = 1; o <= 16; o <<= 1) {
            D += __shfl_xor_sync(0xffffffffu, D, o);
            E += __shfl_xor_sync(0xffffffffu, E, o);
            C += __shfl_xor_sync(0xffffffffu, C, o);
        }
        if (lane == 0) sred[w] = make_float4(D, E, C, 0.f);
        __syncthreads();
        const float4 r0 = sred[0], r1 = sred[1], r2 = sred[2], r3 = sred[3];
        const float Dt = (r0.x + r1.x) + (r2.x + r3.x);
        const float Et = (r0.y + r1.y) + (r2.y + r3.y);
        const float Ct = (r0.z + r1.z) + (r2.z + r3.z);

        const float gam = sG1[sT];
        const bool gt = Dt > sVen[sT];
        const float a = gt ? gam : 0.f;
        const float z2 = fmaf(a, fmaf(gam, Dt, -2.0f * Ct), Et);
        const bool gu = z2 > sVen[sU];
        const float gdA = gt ? dt : 0.f;
        const float du = fmaf(-a, dt, eu);
        const float gdB = gu ? du : 0.f;

        const float2 ga = make_float2(gdA, gdA);
        const float2 gb = make_float2(gdB, gdB);
        #pragma unroll
        for (int c4 = 0; c4 < 8; c4++) {
            const float4 aT = kT[c4];
            const float4 aU = kU[c4];
            float2 m0 = M[2 * c4], m1 = M[2 * c4 + 1];
            m0 = fma2(ga, make_float2(aT.x, aT.y), m0);
            m1 = fma2(ga, make_float2(aT.z, aT.w), m1);
            m0 = fma2(gb, make_float2(aU.x, aU.y), m0);
            m1 = fma2(gb, make_float2(aU.z, aU.w), m1);
            M[2 * c4] = m0; M[2 * c4 + 1] = m1;
        }
    }

    // -------- epilogue ----------------------------------------------------
    __syncthreads();
    if (i < 64) sq[i] = g_q[(b << 6) + i];
    __syncthreads();
    {
        const float4* qp = reinterpret_cast<const float4*>(sq) + h * 8;
        float2 p0 = make_float2(0.f, 0.f), p1 = p0;
        #pragma unroll
        for (int c4 = 0; c4 < 8; c4 += 2) {
            const float4 wa = qp[c4];
            const float4 wb = qp[c4 + 1];
            p0 = fma2(M[2 * c4],     make_float2(wa.x, wa.y), p0);
            p1 = fma2(M[2 * c4 + 1], make_float2(wa.z, wa.w), p1);
            p0 = fma2(M[2 * c4 + 2], make_float2(wb.x, wb.y), p0);
            p1 = fma2(M[2 * c4 + 3], make_float2(wb.z, wb.w), p1);
        }
        float mq = (p0.x + p0.y) + (p1.x + p1.y);
        mq += __shfl_xor_sync(0xffffffffu, mq, 1);
        if (h == 0) sr[p] = mq;
    }
    __syncthreads();
    if (i < 64) {
        float r = rpb[i];
        for (int jj = 0; jj < 64; jj++) r = fmaf(sr[jj], rpW[jj * 64 + i], r);
        __syncwarp(0xffffffffu);
        sq[i] = r;
    }
    __syncthreads();
    if (i < 64) {
        float o = outb[i];
        for (int jj = 0; jj < 64; jj++) o = fmaf(sq[jj], outW[jj * 64 + i], o);
        out[(b << 6) + i] = o;
    }
}

// ---------------------------------------------------------------------------
extern "C" void kernel_launch(void* const* d_in, const int* in_sizes, int n_in,
                              void* d_out, int out_size)
{
    const int*   seq    = (const int*)  d_in[0];
    const float* embedW = (const float*)d_in[1];
    const float* W1     = (const float*)d_in[2];
    const float* b1     = (const float*)d_in[3];
    const float* W2     = (const float*)d_in[4];
    const float* b2     = (const float*)d_in[5];
    const float* lng    = (const float*)d_in[6];
    const float* lnb    = (const float*)d_in[7];
    const float* kpW    = (const float*)d_in[8];
    const float* vpW    = (const float*)d_in[9];
    const float* qpW    = (const float*)d_in[10];
    const float* rpW    = (const float*)d_in[11];
    const float* rpb    = (const float*)d_in[12];
    const float* outW   = (const float*)d_in[13];
    const float* outb   = (const float*)d_in[14];
    float* out = (float*)d_out;

    const int smem = SMEM_TOK_FLOATS * (int)sizeof(float);   // 201984 B
    cudaFuncSetAttribute(k_tokens, cudaFuncAttributeMaxDynamicSharedMemorySize, smem);

    k_tokens<<<512, 256, smem>>>(seq, embedW, W1, b1, W2, b2, lng, lnb, kpW, vpW, qpW);
    k_gamma<<<256, 256>>>();
    k_scan<<<64, 128>>>(rpW, rpb, outW, outb, out);
}

// round 12
// speedup vs baseline: 1.1100x; 1.0683x over previous
#include <cuda_runtime.h>
#include <cstdint>
#include <cstddef>

#define BB 64
#define LL 1024
#define HH 64
#define LM1 1023
#define CH 32            // scan staging chunk (steps)
#define TPC 128          // tokens per CTA in k_tokens
#define RP 132           // padded row length (floats) for transposed smem tiles

// Scratch (device globals — the allowed scratch mechanism). Zero-initialized.
__device__ float g_k   [BB * LM1 * HH + 8 * HH];  // pre-normalized keys (+pad for d<=7 Gram reads)
__device__ float g_v   [BB * LM1 * HH + 2 * HH];  // values
__device__ float g_ven [BB * 1024];               // 0.16*||v||^2
__device__ float g_gamA[7ull * BB * 1024];        // G_d[b][t] = <kn_t, kn_{t+d}>, d=1..7
__device__ float g_q   [BB * HH];

// Packed f32x2 FMA
__device__ __forceinline__ float2 fma2(float2 a, float2 b, float2 c) {
    float2 d;
    asm("fma.rn.f32x2 %0, %1, %2, %3;"
        : "=l"(*reinterpret_cast<unsigned long long*>(&d))
        : "l"(*reinterpret_cast<unsigned long long*>(&a)),
          "l"(*reinterpret_cast<unsigned long long*>(&b)),
          "l"(*reinterpret_cast<unsigned long long*>(&c)));
    return d;
}

__device__ __forceinline__ void cp16(uint32_t dst, const void* src) {
    asm volatile("cp.async.cg.shared.global [%0], [%1], 16;" :: "r"(dst), "l"(src));
}

// Shared-memory float offsets for k_tokens (total 50496 floats = 197.25 KB)
#define OFF_WA   0
#define OFF_WB   8192
#define OFF_HT   16384
#define OFF_ST   24832
#define OFF_FFT  41728
#define OFF_B1   50176
#define OFF_B2   50304
#define OFF_G    50368
#define OFF_BT   50432
#define SMEM_TOK_FLOATS 50496

// ---------------------------------------------------------------------------
// Kernel 1: cooperative register-tiled GEMM pipeline (unchanged from R8).
// ---------------------------------------------------------------------------
__global__ __launch_bounds__(256, 1)
void k_tokens(const int*   __restrict__ seq,
              const float* __restrict__ embedW,
              const float* __restrict__ W1,
              const float* __restrict__ b1,
              const float* __restrict__ W2,
              const float* __restrict__ b2,
              const float* __restrict__ lng,
              const float* __restrict__ lnb,
              const float* __restrict__ kpW,
              const float* __restrict__ vpW,
              const float* __restrict__ qpW)
{
    extern __shared__ float sm[];
    const int tid = threadIdx.x;
    const int cta = blockIdx.x;
    const int b = cta >> 3;
    const int tbase = (cta & 7) * TPC;

    const uint32_t smA = (uint32_t)__cvta_generic_to_shared(sm + OFF_WA);
    const uint32_t smB = (uint32_t)__cvta_generic_to_shared(sm + OFF_WB);

    #pragma unroll
    for (int r = 0; r < 8; r++) {
        cp16(smA + (tid + 256 * r) * 16, (const char*)W1 + (tid + 256 * r) * 16);
        cp16(smB + (tid + 256 * r) * 16, (const char*)W2 + (tid + 256 * r) * 16);
    }
    asm volatile("cp.async.commit_group;" ::: "memory");

    if (tid < 128) sm[OFF_B1 + tid] = b1[tid];
    if (tid < 64) {
        sm[OFF_B2 + tid] = b2[tid];
        sm[OFF_G  + tid] = lng[tid];
        sm[OFF_BT + tid] = lnb[tid];
    }

    const int tok  = tid >> 1;
    const int half = tid & 1;
    {
        const int sidx = seq[(b << 10) + tbase + tok];
        const float4* e4 = reinterpret_cast<const float4*>(embedW + (sidx << 6) + half * 32);
        float* ht = sm + OFF_HT;
        #pragma unroll
        for (int r = 0; r < 8; r++) {
            float4 w = e4[r];
            int k = half * 32 + r * 4;
            ht[(k + 0) * RP + tok] = w.x;
            ht[(k + 1) * RP + tok] = w.y;
            ht[(k + 2) * RP + tok] = w.z;
            ht[(k + 3) * RP + tok] = w.w;
        }
    }
    asm volatile("cp.async.wait_group 0;" ::: "memory");
    __syncthreads();

    // ---- GEMM1 -----------------------------------------------------------
    {
        const int m0 = (tid & 15) * 8;
        const int n0 = (tid >> 4) * 8;
        float2 c1[8][4];
        #pragma unroll
        for (int ni = 0; ni < 8; ni++)
            #pragma unroll
            for (int mj = 0; mj < 4; mj++) c1[ni][mj] = make_float2(0.f, 0.f);

        const float4* ht4 = reinterpret_cast<const float4*>(sm + OFF_HT);
        const float4* w14 = reinterpret_cast<const float4*>(sm + OFF_WA);
        #pragma unroll 4
        for (int k = 0; k < 64; k++) {
            const float4 a0 = ht4[k * (RP / 4) + m0 / 4];
            const float4 a1 = ht4[k * (RP / 4) + m0 / 4 + 1];
            const float2 am[4] = { {a0.x, a0.y}, {a0.z, a0.w}, {a1.x, a1.y}, {a1.z, a1.w} };
            const float4 b0 = w14[k * 32 + n0 / 4];
            const float4 bq = w14[k * 32 + n0 / 4 + 1];
            const float bn[8] = { b0.x, b0.y, b0.z, b0.w, bq.x, bq.y, bq.z, bq.w };
            #pragma unroll
            for (int ni = 0; ni < 8; ni++) {
                const float2 bb = make_float2(bn[ni], bn[ni]);
                #pragma unroll
                for (int mj = 0; mj < 4; mj++)
                    c1[ni][mj] = fma2(bb, am[mj], c1[ni][mj]);
            }
        }
        float4* st4 = reinterpret_cast<float4*>(sm + OFF_ST);
        #pragma unroll
        for (int ni = 0; ni < 8; ni++) {
            const float bb = sm[OFF_B1 + n0 + ni];
            float2 r0 = c1[ni][0], r1 = c1[ni][1], r2 = c1[ni][2], r3 = c1[ni][3];
            r0.x = fmaxf(r0.x + bb, 0.f); r0.y = fmaxf(r0.y + bb, 0.f);
            r1.x = fmaxf(r1.x + bb, 0.f); r1.y = fmaxf(r1.y + bb, 0.f);
            r2.x = fmaxf(r2.x + bb, 0.f); r2.y = fmaxf(r2.y + bb, 0.f);
            r3.x = fmaxf(r3.x + bb, 0.f); r3.y = fmaxf(r3.y + bb, 0.f);
            st4[(n0 + ni) * (RP / 4) + m0 / 4]     = make_float4(r0.x, r0.y, r1.x, r1.y);
            st4[(n0 + ni) * (RP / 4) + m0 / 4 + 1] = make_float4(r2.x, r2.y, r3.x, r3.y);
        }
    }
    __syncthreads();

    // ---- prefetch KV-combined weights [64][128] (2048 float4s) -----------
    {
        #pragma unroll
        for (int r = 0; r < 8; r++) {
            const int f = tid + 256 * r;
            const int k = f >> 5;
            const int c4 = f & 31;
            const char* src = (c4 < 16)
                ? (const char*)kpW + (k * 16 + c4) * 16
                : (const char*)vpW + (k * 16 + (c4 - 16)) * 16;
            cp16(smA + f * 16, src);
        }
        asm volatile("cp.async.commit_group;" ::: "memory");
    }

    // ---- GEMM2 -----------------------------------------------------------
    {
        const int m0 = (tid >> 4) * 8;
        const int n0 = (tid & 15) * 4;
        float2 c2[4][4];
        #pragma unroll
        for (int ni = 0; ni < 4; ni++)
            #pragma unroll
            for (int mj = 0; mj < 4; mj++) c2[ni][mj] = make_float2(0.f, 0.f);

        const float4* st4 = reinterpret_cast<const float4*>(sm + OFF_ST);
        const float4* w24 = reinterpret_cast<const float4*>(sm + OFF_WB);
        #pragma unroll 4
        for (int k = 0; k < 128; k++) {
            const float4 a0 = st4[k * (RP / 4) + m0 / 4];
            const float4 a1 = st4[k * (RP / 4) + m0 / 4 + 1];
            const float2 am[4] = { {a0.x, a0.y}, {a0.z, a0.w}, {a1.x, a1.y}, {a1.z, a1.w} };
            const float4 b0 = w24[k * 16 + n0 / 4];
            const float bn[4] = { b0.x, b0.y, b0.z, b0.w };
            #pragma unroll
            for (int ni = 0; ni < 4; ni++) {
                const float2 bb = make_float2(bn[ni], bn[ni]);
                #pragma unroll
                for (int mj = 0; mj < 4; mj++)
                    c2[ni][mj] = fma2(bb, am[mj], c2[ni][mj]);
            }
        }
        float4* ff4 = reinterpret_cast<float4*>(sm + OFF_FFT);
        #pragma unroll
        for (int ni = 0; ni < 4; ni++) {
            const float bb = sm[OFF_B2 + n0 + ni];
            float2 r0 = c2[ni][0], r1 = c2[ni][1], r2 = c2[ni][2], r3 = c2[ni][3];
            r0.x += bb; r0.y += bb; r1.x += bb; r1.y += bb;
            r2.x += bb; r2.y += bb; r3.x += bb; r3.y += bb;
            ff4[(n0 + ni) * (RP / 4) + m0 / 4]     = make_float4(r0.x, r0.y, r1.x, r1.y);
            ff4[(n0 + ni) * (RP / 4) + m0 / 4 + 1] = make_float4(r2.x, r2.y, r3.x, r3.y);
        }
    }
    __syncthreads();

    // ---- LayerNorm per token ---------------------------------------------
    {
        float x[32];
        const float* ht = sm + OFF_HT;
        const float* ff = sm + OFF_FFT;
        #pragma unroll
        for (int j = 0; j < 32; j++) {
            const int k = half * 32 + j;
            x[j] = ht[k * RP + tok] + ff[k * RP + tok];
        }
        float s1 = 0.f;
        #pragma unroll
        for (int j = 0; j < 32; j++) s1 += x[j];
        s1 += __shfl_xor_sync(0xffffffffu, s1, 1);
        const float mu = s1 * (1.0f / 64.0f);
        float s2 = 0.f;
        #pragma unroll
        for (int j = 0; j < 32; j++) { const float dx = x[j] - mu; s2 += dx * dx; }
        s2 += __shfl_xor_sync(0xffffffffu, s2, 1);
        const float inv = 1.0f / sqrtf(s2 * (1.0f / 64.0f) + 1e-5f);
        float* hw = sm + OFF_HT;
        #pragma unroll
        for (int j = 0; j < 32; j++) {
            const int k = half * 32 + j;
            hw[k * RP + tok] = (x[j] - mu) * inv * sm[OFF_G + k] + sm[OFF_BT + k];
        }
    }
    asm volatile("cp.async.wait_group 0;" ::: "memory");
    __syncthreads();

    // ---- GEMM3: K|V ------------------------------------------------------
    {
        const int m0 = (tid & 15) * 8;
        const int n0 = (tid >> 4) * 8;
        float2 c3[8][4];
        #pragma unroll
        for (int ni = 0; ni < 8; ni++)
            #pragma unroll
            for (int mj = 0; mj < 4; mj++) c3[ni][mj] = make_float2(0.f, 0.f);

        const float4* ht4 = reinterpret_cast<const float4*>(sm + OFF_HT);
        const float4* wk4 = reinterpret_cast<const float4*>(sm + OFF_WA);
        #pragma unroll 4
        for (int k = 0; k < 64; k++) {
            const float4 a0 = ht4[k * (RP / 4) + m0 / 4];
            const float4 a1 = ht4[k * (RP / 4) + m0 / 4 + 1];
            const float2 am[4] = { {a0.x, a0.y}, {a0.z, a0.w}, {a1.x, a1.y}, {a1.z, a1.w} };
            const float4 b0 = wk4[k * 32 + n0 / 4];
            const float4 bq = wk4[k * 32 + n0 / 4 + 1];
            const float bn[8] = { b0.x, b0.y, b0.z, b0.w, bq.x, bq.y, bq.z, bq.w };
            #pragma unroll
            for (int ni = 0; ni < 8; ni++) {
                const float2 bb = make_float2(bn[ni], bn[ni]);
                #pragma unroll
                for (int mj = 0; mj < 4; mj++)
                    c3[ni][mj] = fma2(bb, am[mj], c3[ni][mj]);
            }
        }
        float4* kv4 = reinterpret_cast<float4*>(sm + OFF_ST);
        #pragma unroll
        for (int ni = 0; ni < 8; ni++) {
            const float2 r0 = c3[ni][0], r1 = c3[ni][1], r2 = c3[ni][2], r3 = c3[ni][3];
            kv4[(n0 + ni) * (RP / 4) + m0 / 4]     = make_float4(r0.x, r0.y, r1.x, r1.y);
            kv4[(n0 + ni) * (RP / 4) + m0 / 4 + 1] = make_float4(r2.x, r2.y, r3.x, r3.y);
        }
    }
    __syncthreads();

    // ---- k-normalize, ven, stores ----------------------------------------
    {
        const int t = tbase + tok;
        const float* kv = sm + OFF_ST;
        float kvv[32];
        float nk = 0.f;
        #pragma unroll
        for (int j = 0; j < 32; j++) {
            kvv[j] = kv[(half * 32 + j) * RP + tok];
            nk = fmaf(kvv[j], kvv[j], nk);
        }
        nk += __shfl_xor_sync(0xffffffffu, nk, 1);
        const float kinv = 1.0f / fmaxf(sqrtf(nk), 1e-12f);
        if (t < LM1) {
            const size_t base = ((size_t)(b * LM1 + t)) << 6;
            float4* gk4 = reinterpret_cast<float4*>(g_k + base + half * 32);
            #pragma unroll
            for (int j4 = 0; j4 < 8; j4++) {
                gk4[j4] = make_float4(kvv[4 * j4] * kinv, kvv[4 * j4 + 1] * kinv,
                                      kvv[4 * j4 + 2] * kinv, kvv[4 * j4 + 3] * kinv);
            }
        }
        float nv = 0.f;
        #pragma unroll
        for (int j = 0; j < 32; j++) {
            kvv[j] = kv[(64 + half * 32 + j) * RP + tok];
            nv = fmaf(kvv[j], kvv[j], nv);
        }
        const float nvt = nv + __shfl_xor_sync(0xffffffffu, nv, 1);
        if (t < LM1) {
            const size_t base = ((size_t)(b * LM1 + t)) << 6;
            float4* gv4 = reinterpret_cast<float4*>(g_v + base + half * 32);
            #pragma unroll
            for (int j4 = 0; j4 < 8; j4++) {
                gv4[j4] = make_float4(kvv[4 * j4], kvv[4 * j4 + 1],
                                      kvv[4 * j4 + 2], kvv[4 * j4 + 3]);
            }
            if (half == 0) g_ven[(b << 10) + t] = 0.16f * nvt;
        }
    }

    // ---- q projection ----------------------------------------------------
    if ((cta & 7) == 7 && tid < 64) {
        const float* ht = sm + OFF_HT;
        float a0 = 0.f, a1 = 0.f, a2 = 0.f, a3 = 0.f;
        #pragma unroll 8
        for (int k = 0; k < 64; k += 4) {
            a0 = fmaf(ht[(k + 0) * RP + 127], __ldg(qpW + (k + 0) * 64 + tid), a0);
            a1 = fmaf(ht[(k + 1) * RP + 127], __ldg(qpW + (k + 1) * 64 + tid), a1);
            a2 = fmaf(ht[(k + 2) * RP + 127], __ldg(qpW + (k + 2) * 64 + tid), a2);
            a3 = fmaf(ht[(k + 3) * RP + 127], __ldg(qpW + (k + 3) * 64 + tid), a3);
        }
        g_q[(b << 6) + tid] = (a0 + a1) + (a2 + a3);
    }
}

// ---------------------------------------------------------------------------
// Kernel 1b: key Gram at distances 1..7 (for lookahead-block corrections).
// ---------------------------------------------------------------------------
__global__ __launch_bounds__(256, 1)
void k_gamma()
{
    const int idx = blockIdx.x * 256 + threadIdx.x;
    const int b = idx >> 10;
    const int t = idx & 1023;
    float dd[7] = {0.f, 0.f, 0.f, 0.f, 0.f, 0.f, 0.f};
    if (t <= 1021) {
        const float4* a = reinterpret_cast<const float4*>(g_k + (((size_t)(b * LM1 + t)) << 6));
        float4 x[16];
        #pragma unroll
        for (int k = 0; k < 16; k++) x[k] = a[k];
        #pragma unroll
        for (int d = 1; d <= 7; d++) {
            float s = 0.f;
            const float4* y = a + d * 16;   // padded array: always in-bounds
            #pragma unroll
            for (int k = 0; k < 16; k++) {
                const float4 yy = y[k];
                s = fmaf(x[k].x, yy.x, fmaf(x[k].y, yy.y, fmaf(x[k].z, yy.z, fmaf(x[k].w, yy.w, s))));
            }
            dd[d - 1] = s;
        }
    }
    #pragma unroll
    for (int d = 1; d <= 7; d++)
        g_gamA[(size_t)(d - 1) * (BB << 10) + (b << 10) + t] = (t + d <= 1022) ? dd[d - 1] : 0.f;
}

// ---------------------------------------------------------------------------
// Kernel 2: gated fast-weight scan — 4-step blocks, FULL LOOKAHEAD, 64 thr.
// Batch (gate-independent): apply block j-1's 4 rank-1 updates -> M_{t-1};
//   raw e''_m = v_{t+4+m} - M_{t-1} kn_{t+4+m}  for block j+1.
// Serial: e_m = e''_m - sum_i gdPrev_i * G(4+m-i) (16 fma w/ precomputed Gram)
//   -> 10-value Gram tree -> ONE barrier -> 4-gate resolve (R11 algebra)
//   -> forward-substituted d's -> pending gd.
// Batch overlaps the tree (independent, same basic block, pre-barrier).
// ---------------------------------------------------------------------------
__global__ __launch_bounds__(64, 1)
void k_scan(const float* __restrict__ rpW,
            const float* __restrict__ rpb,
            const float* __restrict__ outW,
            const float* __restrict__ outb,
            float* __restrict__ out)
{
    __shared__ float sK[2 * CH][64];
    __shared__ float sV[2 * CH][64];
    __shared__ float sVen[2 * CH];
    __shared__ float sG[7][2 * CH];
    __shared__ float sredE[2][2][12];   // [parity][warp][10 padded]
    __shared__ float sq[64];
    __shared__ float sr[64];

    const int i = threadIdx.x;
    const int b = blockIdx.x;
    const int lane = i & 31, w = i >> 5;

    const size_t base = (size_t)b * LM1 * 64;
    const int vb = b << 10;

    const uint32_t aK   = (uint32_t)__cvta_generic_to_shared(&sK[0][0]);
    const uint32_t aV   = (uint32_t)__cvta_generic_to_shared(&sV[0][0]);
    const uint32_t aVen = (uint32_t)__cvta_generic_to_shared(&sVen[0]);
    const uint32_t aG   = (uint32_t)__cvta_generic_to_shared(&sG[0][0]);

    auto stage = [&](int q) {
        const int hb = (q & 1) * (CH * 64 * 4);
        const int hs = (q & 1) * (CH * 4);
        const char* gk = (const char*)(g_k + base) + ((size_t)q << 13);
        const char* gv = (const char*)(g_v + base) + ((size_t)q << 13);
        #pragma unroll
        for (int r = 0; r < 8; r++) {
            cp16(aK + hb + i * 16 + r * 1024, gk + i * 16 + r * 1024);
            cp16(aV + hb + i * 16 + r * 1024, gv + i * 16 + r * 1024);
        }
        {   // small arrays: ven + G1..G7 = 8 arrays x 8 float4 = 64 cp16
            const int arr = i >> 3;       // 0..7
            const int part = i & 7;       // 0..7
            const char* src = (arr == 0)
                ? (const char*)(g_ven + vb + q * CH)
                : (const char*)(g_gamA + (size_t)(arr - 1) * (BB << 10) + vb + q * CH);
            const uint32_t dst = (arr == 0)
                ? (aVen + hs + part * 16)
                : (aG + (uint32_t)(arr - 1) * (2 * CH * 4) + hs + part * 16);
            cp16(dst, src + part * 16);
        }
        asm volatile("cp.async.commit_group;" ::: "memory");
    };

    float2 M[32];
    #pragma unroll
    for (int c = 0; c < 32; c++) M[c] = make_float2(0.f, 0.f);

    stage(0);
    asm volatile("cp.async.wait_group 0;" ::: "memory");
    __syncthreads();

    // ---- prologue: block 0 raw residuals (M = 0 -> e'' = v) --------------
    float ep0 = sV[0][i], ep1 = sV[1][i], ep2 = sV[2][i], ep3 = sV[3][i];
    float gdP0 = 0.f, gdP1 = 0.f, gdP2 = 0.f, gdP3 = 0.f;

    // ---- main loop: 255 blocks of 4 steps, t = 0,4,...,1016 ---------------
    for (int j = 0; j < 255; j++) {
        const int t = 4 * j;
        if ((t & 31) == 28) {                 // batch reads keys t+4..t+7 in next chunk
            asm volatile("cp.async.wait_group 0;" ::: "memory");
            __syncthreads();
        }
        if ((t & 31) == 4) {
            const int qn = (t >> 5) + 1;
            if (qn < 32) stage(qn);
        }

        // ---- serial: Gram-correct raw residuals with gdPrev --------------
        float e0, e1, e2, e3;
        if (j) {
            const int b0 = (t - 4) & 63, b1 = (t - 3) & 63, b2 = (t - 2) & 63, b3 = (t - 1) & 63;
            e0 = ep0 - (gdP0 * sG[3][b0] + gdP1 * sG[2][b1] + gdP2 * sG[1][b2] + gdP3 * sG[0][b3]);
            e1 = ep1 - (gdP0 * sG[4][b0] + gdP1 * sG[3][b1] + gdP2 * sG[2][b2] + gdP3 * sG[1][b3]);
            e2 = ep2 - (gdP0 * sG[5][b0] + gdP1 * sG[4][b1] + gdP2 * sG[3][b2] + gdP3 * sG[2][b3]);
            e3 = ep3 - (gdP0 * sG[6][b0] + gdP1 * sG[5][b1] + gdP2 * sG[4][b2] + gdP3 * sG[3][b3]);
        } else {
            e0 = ep0; e1 = ep1; e2 = ep2; e3 = ep3;
        }

        // ---- serial: 10-value Gram tree ----------------------------------
        float E00 = e0 * e0, E01 = e0 * e1, E02 = e0 * e2, E03 = e0 * e3;
        float E11 = e1 * e1, E12 = e1 * e2, E13 = e1 * e3;
        float E22 = e2 * e2, E23 = e2 * e3;
        float E33 = e3 * e3;
        #pragma unroll
        for (int o = 1; o <= 16; o <<= 1) {
            E00 += __shfl_xor_sync(0xffffffffu, E00, o);
            E01 += __shfl_xor_sync(0xffffffffu, E01, o);
            E02 += __shfl_xor_sync(0xffffffffu, E02, o);
            E03 += __shfl_xor_sync(0xffffffffu, E03, o);
            E11 += __shfl_xor_sync(0xffffffffu, E11, o);
            E12 += __shfl_xor_sync(0xffffffffu, E12, o);
            E13 += __shfl_xor_sync(0xffffffffu, E13, o);
            E22 += __shfl_xor_sync(0xffffffffu, E22, o);
            E23 += __shfl_xor_sync(0xffffffffu, E23, o);
            E33 += __shfl_xor_sync(0xffffffffu, E33, o);
        }
        const int pb = j & 1;
        if (lane == 0) {
            float* dst = sredE[pb][w];
            dst[0] = E00; dst[1] = E01; dst[2] = E02; dst[3] = E03;
            dst[4] = E11; dst[5] = E12; dst[6] = E13; dst[7] = E22;
            dst[8] = E23; dst[9] = E33;
        }

        // ---- batch (gate-independent; overlaps the tree above) -----------
        // 1) apply block j-1's pending updates -> M_{t-1}
        {
            const int sp0 = j ? ((t - 4) & 63) : 0;
            const int sp1 = j ? ((t - 3) & 63) : 0;
            const int sp2 = j ? ((t - 2) & 63) : 0;
            const int sp3 = j ? ((t - 1) & 63) : 0;
            const float4* k0 = reinterpret_cast<const float4*>(sK[sp0]);
            const float4* k1 = reinterpret_cast<const float4*>(sK[sp1]);
            const float4* k2 = reinterpret_cast<const float4*>(sK[sp2]);
            const float4* k3 = reinterpret_cast<const float4*>(sK[sp3]);
            const float2 g0 = make_float2(gdP0, gdP0);
            const float2 g1 = make_float2(gdP1, gdP1);
            const float2 g2 = make_float2(gdP2, gdP2);
            const float2 g3 = make_float2(gdP3, gdP3);
            #pragma unroll
            for (int c = 0; c < 16; c++) {
                const float4 a0 = k0[c];
                const float4 a1 = k1[c];
                const float4 a2 = k2[c];
                const float4 a3 = k3[c];
                float2 m0 = M[2 * c], m1 = M[2 * c + 1];
                m0 = fma2(g0, make_float2(a0.x, a0.y), m0);
                m1 = fma2(g0, make_float2(a0.z, a0.w), m1);
                m0 = fma2(g1, make_float2(a1.x, a1.y), m0);
                m1 = fma2(g1, make_float2(a1.z, a1.w), m1);
                m0 = fma2(g2, make_float2(a2.x, a2.y), m0);
                m1 = fma2(g2, make_float2(a2.z, a2.w), m1);
                m0 = fma2(g3, make_float2(a3.x, a3.y), m0);
                m1 = fma2(g3, make_float2(a3.z, a3.w), m1);
                M[2 * c] = m0; M[2 * c + 1] = m1;
            }
        }
        // 2) raw residuals for block j+1 (keys t+4..t+7; padded OOB-safe)
        {
            const int n0 = (t + 4) & 63, n1 = (t + 5) & 63, n2 = (t + 6) & 63, n3 = (t + 7) & 63;
            const float4* k0 = reinterpret_cast<const float4*>(sK[n0]);
            const float4* k1 = reinterpret_cast<const float4*>(sK[n1]);
            const float4* k2 = reinterpret_cast<const float4*>(sK[n2]);
            const float4* k3 = reinterpret_cast<const float4*>(sK[n3]);
            float2 u0 = make_float2(0.f, 0.f), u1 = u0, u2 = u0, u3 = u0;
            #pragma unroll
            for (int c = 0; c < 16; c++) {
                const float2 ma = M[2 * c];
                const float2 mb = M[2 * c + 1];
                const float4 a0 = k0[c];
                const float4 a1 = k1[c];
                const float4 a2 = k2[c];
                const float4 a3 = k3[c];
                u0 = fma2(ma, make_float2(a0.x, a0.y), u0);
                u0 = fma2(mb, make_float2(a0.z, a0.w), u0);
                u1 = fma2(ma, make_float2(a1.x, a1.y), u1);
                u1 = fma2(mb, make_float2(a1.z, a1.w), u1);
                u2 = fma2(ma, make_float2(a2.x, a2.y), u2);
                u2 = fma2(mb, make_float2(a2.z, a2.w), u2);
                u3 = fma2(ma, make_float2(a3.x, a3.y), u3);
                u3 = fma2(mb, make_float2(a3.z, a3.w), u3);
            }
            ep0 = sV[n0][i] - (u0.x + u0.y);
            ep1 = sV[n1][i] - (u1.x + u1.y);
            ep2 = sV[n2][i] - (u2.x + u2.y);
            ep3 = sV[n3][i] - (u3.x + u3.y);
        }

        __syncthreads();                      // the ONLY barrier per 4 steps

        // ---- combine partials + resolve 4 gates (R11 algebra) ------------
        {
            const float* r0 = sredE[pb][0];
            const float* r1 = sredE[pb][1];
            E00 = r0[0] + r1[0]; E01 = r0[1] + r1[1]; E02 = r0[2] + r1[2];
            E03 = r0[3] + r1[3]; E11 = r0[4] + r1[4]; E12 = r0[5] + r1[5];
            E13 = r0[6] + r1[6]; E22 = r0[7] + r1[7]; E23 = r0[8] + r1[8];
            E33 = r0[9] + r1[9];
        }
        const int sT0 = t & 63, sT1 = (t + 1) & 63, sT2 = (t + 2) & 63, sT3 = (t + 3) & 63;
        const float G01 = sG[0][sT0], G12 = sG[0][sT1], G23 = sG[0][sT2];
        const float G02 = sG[1][sT0], G13 = sG[1][sT1], G03 = sG[2][sT0];
        const float v0 = sVen[sT0], v1 = sVen[sT1], v2 = sVen[sT2], v3 = sVen[sT3];

        const bool g0 = E00 > v0;
        const float c01 = g0 ? G01 : 0.f, c02 = g0 ? G02 : 0.f, c03 = g0 ? G03 : 0.f;
        const float D1 = E11 - 2.f * c01 * E01 + c01 * c01 * E00;
        const bool g1 = D1 > v1;
        const float c12 = g1 ? G12 : 0.f, c13 = g1 ? G13 : 0.f;
        const float a20 = c12 * c01 - c02, a21 = -c12;
        const float D2 = a20 * a20 * E00 + a21 * a21 * E11 + E22
                       + 2.f * (a20 * a21 * E01 + a20 * E02 + a21 * E12);
        const bool g2 = D2 > v2;
        const float c23 = g2 ? G23 : 0.f;
        const float a30 = c13 * c01 - c03 - c23 * a20;
        const float a31 = -c13 - c23 * a21;
        const float a32 = -c23;
        const float D3 = a30 * a30 * E00 + a31 * a31 * E11 + a32 * a32 * E22 + E33
                       + 2.f * (a30 * a31 * E01 + a30 * a32 * E02 + a30 * E03
                              + a31 * a32 * E12 + a31 * E13 + a32 * E23);
        const bool g3 = D3 > v3;

        const float d0c = e0;
        const float d1c = e1 - c01 * d0c;
        const float d2c = e2 - c02 * d0c - c12 * d1c;
        const float d3c = e3 - c03 * d0c - c13 * d1c - c23 * d2c;
        gdP0 = g0 ? d0c : 0.f;
        gdP1 = g1 ? d1c : 0.f;
        gdP2 = g2 ? d2c : 0.f;
        gdP3 = g3 ? d3c : 0.f;
    }

    // ---- tail: steps 1020..1022 ------------------------------------------
    {
        // corrections with gd from block 254 (steps 1016..1019)
        const int b0 = 1016 & 63, b1 = 1017 & 63, b2 = 1018 & 63, b3 = 1019 & 63;
        const float e0 = ep0 - (gdP0 * sG[3][b0] + gdP1 * sG[2][b1] + gdP2 * sG[1][b2] + gdP3 * sG[0][b3]);
        const float e1 = ep1 - (gdP0 * sG[4][b0] + gdP1 * sG[3][b1] + gdP2 * sG[2][b2] + gdP3 * sG[1][b3]);
        const float e2 = ep2 - (gdP0 * sG[5][b0] + gdP1 * sG[4][b1] + gdP2 * sG[3][b2] + gdP3 * sG[2][b3]);

        // apply pending updates (keys 1016..1019)
        {
            const float4* k0 = reinterpret_cast<const float4*>(sK[b0]);
            const float4* k1 = reinterpret_cast<const float4*>(sK[b1]);
            const float4* k2 = reinterpret_cast<const float4*>(sK[b2]);
            const float4* k3 = reinterpret_cast<const float4*>(sK[b3]);
            const float2 g0 = make_float2(gdP0, gdP0);
            const float2 g1 = make_float2(gdP1, gdP1);
            const float2 g2 = make_float2(gdP2, gdP2);
            const float2 g3 = make_float2(gdP3, gdP3);
            #pragma unroll
            for (int c = 0; c < 16; c++) {
                const float4 a0 = k0[c];
                const float4 a1 = k1[c];
                const float4 a2 = k2[c];
                const float4 a3 = k3[c];
                float2 m0 = M[2 * c], m1 = M[2 * c + 1];
                m0 = fma2(g0, make_float2(a0.x, a0.y), m0);
                m1 = fma2(g0, make_float2(a0.z, a0.w), m1);
                m0 = fma2(g1, make_float2(a1.x, a1.y), m0);
                m1 = fma2(g1, make_float2(a1.z, a1.w), m1);
                m0 = fma2(g2, make_float2(a2.x, a2.y), m0);
                m1 = fma2(g2, make_float2(a2.z, a2.w), m1);
                m0 = fma2(g3, make_float2(a3.x, a3.y), m0);
                m1 = fma2(g3, make_float2(a3.z, a3.w), m1);
                M[2 * c] = m0; M[2 * c + 1] = m1;
            }
        }

        // 6-value Gram tree for 3 remaining gates
        float E00 = e0 * e0, E01 = e0 * e1, E02 = e0 * e2;
        float E11 = e1 * e1, E12 = e1 * e2, E22 = e2 * e2;
        #pragma unroll
        for (int o = 1; o <= 16; o <<= 1) {
            E00 += __shfl_xor_sync(0xffffffffu, E00, o);
            E01 += __shfl_xor_sync(0xffffffffu, E01, o);
            E02 += __shfl_xor_sync(0xffffffffu, E02, o);
            E11 += __shfl_xor_sync(0xffffffffu, E11, o);
            E12 += __shfl_xor_sync(0xffffffffu, E12, o);
            E22 += __shfl_xor_sync(0xffffffffu, E22, o);
        }
        if (lane == 0) {
            float* dst = sredE[1][w];       // last loop iter (j=254) used parity 0
            dst[0] = E00; dst[1] = E01; dst[2] = E02;
            dst[3] = E11; dst[4] = E12; dst[5] = E22;
        }
        __syncthreads();
        {
            const float* r0 = sredE[1][0];
            const float* r1 = sredE[1][1];
            E00 = r0[0] + r1[0]; E01 = r0[1] + r1[1]; E02 = r0[2] + r1[2];
            E11 = r0[3] + r1[3]; E12 = r0[4] + r1[4]; E22 = r0[5] + r1[5];
        }
        const int sT0 = 1020 & 63, sT1 = 1021 & 63, sT2 = 1022 & 63;
        const float G01 = sG[0][sT0], G12 = sG[0][sT1], G02 = sG[1][sT0];
        const float v0 = sVen[sT0], v1 = sVen[sT1], v2 = sVen[sT2];

        const bool g0 = E00 > v0;
        const float c01 = g0 ? G01 : 0.f, c02 = g0 ? G02 : 0.f;
        const float D1 = E11 - 2.f * c01 * E01 + c01 * c01 * E00;
        const bool g1 = D1 > v1;
        const float c12 = g1 ? G12 : 0.f;
        const float a20 = c12 * c01 - c02, a21 = -c12;
        const float D2 = a20 * a20 * E00 + a21 * a21 * E11 + E22
                       + 2.f * (a20 * a21 * E01 + a20 * E02 + a21 * E12);
        const bool g2 = D2 > v2;

        const float d0c = e0;
        const float d1c = e1 - c01 * d0c;
        const float d2c = e2 - c02 * d0c - c12 * d1c;
        const float t0 = g0 ? d0c : 0.f;
        const float t1 = g1 ? d1c : 0.f;
        const float t2 = g2 ? d2c : 0.f;

        // final updates (keys 1020..1022)
        {
            const float4* k0 = reinterpret_cast<const float4*>(sK[sT0]);
            const float4* k1 = reinterpret_cast<const float4*>(sK[sT1]);
            const float4* k2 = reinterpret_cast<const float4*>(sK[sT2]);
            const float2 g0v = make_float2(t0, t0);
            const float2 g1v = make_float2(t1, t1);
            const float2 g2v = make_float2(t2, t2);
            #pragma unroll
            for (int c = 0; c < 16; c++) {
                const float4 a0 = k0[c];
                const float4 a1 = k1[c];
                const float4 a2 = k2[c];
                float2 m0 = M[2 * c], m1 = M[2 * c + 1];
                m0 = fma2(g0v, make_float2(a0.x, a0.y), m0);
                m1 = fma2(g0v, make_float2(a0.z, a0.w), m1);
                m0 = fma2(g1v, make_float2(a1.x, a1.y), m0);
                m1 = fma2(g1v, make_float2(a1.z, a1.w), m1);
                m0 = fma2(g2v, make_float2(a2.x, a2.y), m0);
                m1 = fma2(g2v, make_float2(a2.z, a2.w), m1);
                M[2 * c] = m0; M[2 * c + 1] = m1;
            }
        }
    }

    // -------- epilogue ----------------------------------------------------
    __syncthreads();
    sq[i] = g_q[(b << 6) + i];
    __syncthreads();
    float mq;
    {
        const float4* qp = reinterpret_cast<const float4*>(sq);
        float2 p0 = make_float2(0.f, 0.f), p1 = p0, p2 = p0, p3 = p0;
        #pragma unroll
        for (int c = 0; c < 16; c += 2) {
            const float4 wa = qp[c];
            const float4 wb = qp[c + 1];
            p0 = fma2(M[2 * c],     make_float2(wa.x, wa.y), p0);
            p1 = fma2(M[2 * c + 1], make_float2(wa.z, wa.w), p1);
            p2 = fma2(M[2 * c + 2], make_float2(wb.x, wb.y), p2);
            p3 = fma2(M[2 * c + 3], make_float2(wb.z, wb.w), p3);
        }
        mq = ((p0.x + p0.y) + (p1.x + p1.y)) + ((p2.x + p2.y) + (p3.x + p3.y));
    }
    __syncthreads();
    sr[i] = mq;
    __syncthreads();
    float r = rpb[i];
    for (int jj = 0; jj < 64; jj++) r = fmaf(sr[jj], rpW[jj * 64 + i], r);
    __syncthreads();
    sr[i] = r;
    __syncthreads();
    float o = outb[i];
    for (int jj = 0; jj < 64; jj++) o = fmaf(sr[jj], outW[jj * 64 + i], o);
    out[(b << 6) + i] = o;
}

// ---------------------------------------------------------------------------
extern "C" void kernel_launch(void* const* d_in, const int* in_sizes, int n_in,
                              void* d_out, int out_size)
{
    const int*   seq    = (const int*)  d_in[0];
    const float* embedW = (const float*)d_in[1];
    const float* W1     = (const float*)d_in[2];
    const float* b1     = (const float*)d_in[3];
    const float* W2     = (const float*)d_in[4];
    const float* b2     = (const float*)d_in[5];
    const float* lng    = (const float*)d_in[6];
    const float* lnb    = (const float*)d_in[7];
    const float* kpW    = (const float*)d_in[8];
    const float* vpW    = (const float*)d_in[9];
    const float* qpW    = (const float*)d_in[10];
    const float* rpW    = (const float*)d_in[11];
    const float* rpb    = (const float*)d_in[12];
    const float* outW   = (const float*)d_in[13];
    const float* outb   = (const float*)d_in[14];
    float* out = (float*)d_out;

    const int smem = SMEM_TOK_FLOATS * (int)sizeof(float);   // 201984 B
    cudaFuncSetAttribute(k_tokens, cudaFuncAttributeMaxDynamicSharedMemorySize, smem);

    k_tokens<<<512, 256, smem>>>(seq, embedW, W1, b1, W2, b2, lng, lnb, kpW, vpW, qpW);
    k_gamma<<<256, 256>>>();
    k_scan<<<64, 64>>>(rpW, rpb, outW, outb, out);
}